// round 1
// baseline (speedup 1.0000x reference)
#include <cuda_runtime.h>
#include <cuda_bf16.h>
#include <cstdint>

// ---------------- problem constants ----------------
#define T_TOK 8192      // B*S tokens
#define D_DIM 2048      // model dim
#define H_DIM 2048      // ffn hidden dim
#define NEXP  7         // routed experts
#define TOPK  3

// ---------------- tiling ----------------
#define BM 128
#define BN 64
#define BK 32

// ---------------- scratch (device globals; no allocation allowed) ----------------
__device__ float g_act[(size_t)T_TOK * H_DIM];   // SwiGLU activations for current expert
__device__ float g_w[NEXP * T_TOK];              // combine weight per (expert, token); 0 if unrouted

// ---------------- helpers ----------------
__device__ __forceinline__ float to_tf32(float x) {
    float r;
    asm("cvt.rna.tf32.f32 %0, %1;" : "=f"(r) : "f"(x));
    return r;
}

__device__ __forceinline__ float silu_f(float z) {
    return z / (1.0f + __expf(-z));
}

__device__ __forceinline__ void mma_tf32(float c[4], const float a[4], const float b[2]) {
    asm volatile(
        "mma.sync.aligned.m16n8k8.row.col.f32.tf32.tf32.f32 "
        "{%0,%1,%2,%3}, {%4,%5,%6,%7}, {%8,%9}, {%0,%1,%2,%3};\n"
        : "+f"(c[0]), "+f"(c[1]), "+f"(c[2]), "+f"(c[3])
        : "r"(__float_as_uint(a[0])), "r"(__float_as_uint(a[1])),
          "r"(__float_as_uint(a[2])), "r"(__float_as_uint(a[3])),
          "r"(__float_as_uint(b[0])), "r"(__float_as_uint(b[1])));
}

// ============================================================================
// Gate: logits = x @ gate_w + gate_b; softmax; top-3 (biased); normalized weights
// One block (128 threads) per token.
// ============================================================================
__global__ void gate_kernel(const float* __restrict__ x,
                            const float* __restrict__ gw,
                            const float* __restrict__ gb,
                            const float* __restrict__ biases) {
    const int t = blockIdx.x;
    const float* xr = x + (size_t)t * D_DIM;

    float p[NEXP];
#pragma unroll
    for (int e = 0; e < NEXP; e++) p[e] = 0.f;

    for (int i = threadIdx.x; i < D_DIM; i += 128) {
        float xv = xr[i];
        const float* g = gw + (size_t)i * NEXP;
#pragma unroll
        for (int e = 0; e < NEXP; e++) p[e] += xv * g[e];
    }

    // warp reduce
#pragma unroll
    for (int off = 16; off > 0; off >>= 1) {
#pragma unroll
        for (int e = 0; e < NEXP; e++)
            p[e] += __shfl_xor_sync(0xffffffffu, p[e], off);
    }

    __shared__ float sm[4][NEXP];
    const int wid = threadIdx.x >> 5, lane = threadIdx.x & 31;
    if (lane == 0) {
#pragma unroll
        for (int e = 0; e < NEXP; e++) sm[wid][e] = p[e];
    }
    __syncthreads();

    if (threadIdx.x == 0) {
        float logit[NEXP];
#pragma unroll
        for (int e = 0; e < NEXP; e++)
            logit[e] = sm[0][e] + sm[1][e] + sm[2][e] + sm[3][e] + gb[e];

        float mx = logit[0];
#pragma unroll
        for (int e = 1; e < NEXP; e++) mx = fmaxf(mx, logit[e]);
        float pr[NEXP], den = 0.f;
#pragma unroll
        for (int e = 0; e < NEXP; e++) { pr[e] = __expf(logit[e] - mx); den += pr[e]; }
#pragma unroll
        for (int e = 0; e < NEXP; e++) pr[e] /= den;

        float bi[NEXP];
#pragma unroll
        for (int e = 0; e < NEXP; e++) bi[e] = pr[e] + biases[e];

        bool used[NEXP] = {false, false, false, false, false, false, false};
        int sel[TOPK];
#pragma unroll
        for (int k = 0; k < TOPK; k++) {
            int best = -1; float bv = -1e30f;
#pragma unroll
            for (int e = 0; e < NEXP; e++) {
                if (!used[e] && bi[e] > bv) { bv = bi[e]; best = e; }
            }
            used[best] = true; sel[k] = best;
        }
        float ws = pr[sel[0]] + pr[sel[1]] + pr[sel[2]];

        float w7[NEXP];
#pragma unroll
        for (int e = 0; e < NEXP; e++) w7[e] = 0.f;
#pragma unroll
        for (int k = 0; k < TOPK; k++) w7[sel[k]] = pr[sel[k]] / ws;

#pragma unroll
        for (int e = 0; e < NEXP; e++) g_w[e * T_TOK + t] = w7[e];
    }
}

// ============================================================================
// GEMM1 fused: act = silu(X @ W1) * (X @ Wg)     [T_TOK, H_DIM]
// X: [T_TOK, D_DIM] row-major fp32; W1/Wg: [D_DIM, H_DIM] row-major fp32
// tf32 mma, fp32 accumulate. Block tile 128x64, K-tile 32. 8 warps (4m x 2n).
// ============================================================================
__global__ void __launch_bounds__(256) gemm1_swiglu(const float* __restrict__ X,
                                                    const float* __restrict__ W1,
                                                    const float* __restrict__ Wg) {
    __shared__ float Xs[BM][BK + 1];     // [m][k]
    __shared__ float W1s[BN][BK + 1];    // [n][k] (transposed)
    __shared__ float Wgs[BN][BK + 1];

    const int m0 = blockIdx.x * BM;
    const int n0 = blockIdx.y * BN;
    const int tid = threadIdx.x;
    const int wid = tid >> 5, lane = tid & 31;
    const int wm = (wid & 3) * 32;   // warp row offset within block tile
    const int wn = (wid >> 2) * 32;  // warp col offset

    float acc1[2][4][4];
    float accg[2][4][4];
#pragma unroll
    for (int i = 0; i < 2; i++)
#pragma unroll
        for (int j = 0; j < 4; j++)
#pragma unroll
            for (int r = 0; r < 4; r++) { acc1[i][j][r] = 0.f; accg[i][j][r] = 0.f; }

    const int xr = tid >> 3;            // 0..31
    const int xc4 = (tid & 7) * 4;      // 0..28
    const int wkr = tid >> 4;           // 0..15
    const int wn4 = (tid & 15) * 4;     // 0..60

    for (int k0 = 0; k0 < D_DIM; k0 += BK) {
        // --- load X tile 128x32 ---
#pragma unroll
        for (int i = 0; i < 4; i++) {
            int row = xr + i * 32;
            float4 v = *(const float4*)(X + (size_t)(m0 + row) * D_DIM + k0 + xc4);
            Xs[row][xc4 + 0] = to_tf32(v.x);
            Xs[row][xc4 + 1] = to_tf32(v.y);
            Xs[row][xc4 + 2] = to_tf32(v.z);
            Xs[row][xc4 + 3] = to_tf32(v.w);
        }
        // --- load W1/Wg tiles 32x64, transpose into [n][k] ---
#pragma unroll
        for (int i = 0; i < 2; i++) {
            int k = wkr + i * 16;
            const float* p1 = W1 + (size_t)(k0 + k) * H_DIM + n0 + wn4;
            float4 v = *(const float4*)p1;
            W1s[wn4 + 0][k] = to_tf32(v.x);
            W1s[wn4 + 1][k] = to_tf32(v.y);
            W1s[wn4 + 2][k] = to_tf32(v.z);
            W1s[wn4 + 3][k] = to_tf32(v.w);
            const float* pg = Wg + (size_t)(k0 + k) * H_DIM + n0 + wn4;
            float4 g = *(const float4*)pg;
            Wgs[wn4 + 0][k] = to_tf32(g.x);
            Wgs[wn4 + 1][k] = to_tf32(g.y);
            Wgs[wn4 + 2][k] = to_tf32(g.z);
            Wgs[wn4 + 3][k] = to_tf32(g.w);
        }
        __syncthreads();

        const int ar = lane >> 2, ak = lane & 3;
#pragma unroll
        for (int kk = 0; kk < BK; kk += 8) {
            float a[2][4];
#pragma unroll
            for (int mf = 0; mf < 2; mf++) {
                int rb = wm + mf * 16;
                a[mf][0] = Xs[rb + ar][kk + ak];
                a[mf][1] = Xs[rb + ar + 8][kk + ak];
                a[mf][2] = Xs[rb + ar][kk + ak + 4];
                a[mf][3] = Xs[rb + ar + 8][kk + ak + 4];
            }
#pragma unroll
            for (int nf = 0; nf < 4; nf++) {
                int nb = wn + nf * 8 + (lane >> 2);
                float b1[2] = { W1s[nb][kk + (lane & 3)], W1s[nb][kk + 4 + (lane & 3)] };
                float bg[2] = { Wgs[nb][kk + (lane & 3)], Wgs[nb][kk + 4 + (lane & 3)] };
#pragma unroll
                for (int mf = 0; mf < 2; mf++) {
                    mma_tf32(acc1[mf][nf], a[mf], b1);
                    mma_tf32(accg[mf][nf], a[mf], bg);
                }
            }
        }
        __syncthreads();
    }

    // epilogue: silu(acc1)*accg -> g_act
#pragma unroll
    for (int mf = 0; mf < 2; mf++) {
        int row0 = m0 + wm + mf * 16 + (lane >> 2);
#pragma unroll
        for (int nf = 0; nf < 4; nf++) {
            int col = n0 + wn + nf * 8 + (lane & 3) * 2;
            float2 v0, v1;
            v0.x = silu_f(acc1[mf][nf][0]) * accg[mf][nf][0];
            v0.y = silu_f(acc1[mf][nf][1]) * accg[mf][nf][1];
            v1.x = silu_f(acc1[mf][nf][2]) * accg[mf][nf][2];
            v1.y = silu_f(acc1[mf][nf][3]) * accg[mf][nf][3];
            *(float2*)(g_act + (size_t)row0 * H_DIM + col) = v0;
            *(float2*)(g_act + (size_t)(row0 + 8) * H_DIM + col) = v1;
        }
    }
}

// ============================================================================
// GEMM2: y = g_act @ W2   [T_TOK, D_DIM]
//   expert < 0  : out = y                     (shared expert, scale 1)
//   expert >= 0 : out += g_w[expert,row] * y  (skip RMW when weight == 0)
// ============================================================================
__global__ void __launch_bounds__(256) gemm2_combine(const float* __restrict__ W2,
                                                     float* __restrict__ out,
                                                     int expert) {
    __shared__ float As[BM][BK + 1];     // activation [m][k]
    __shared__ float Ws[BN][BK + 1];     // W2 transposed [n][k]

    const int m0 = blockIdx.x * BM;
    const int n0 = blockIdx.y * BN;
    const int tid = threadIdx.x;
    const int wid = tid >> 5, lane = tid & 31;
    const int wm = (wid & 3) * 32;
    const int wn = (wid >> 2) * 32;

    float acc[2][4][4];
#pragma unroll
    for (int i = 0; i < 2; i++)
#pragma unroll
        for (int j = 0; j < 4; j++)
#pragma unroll
            for (int r = 0; r < 4; r++) acc[i][j][r] = 0.f;

    const int xr = tid >> 3;
    const int xc4 = (tid & 7) * 4;
    const int wkr = tid >> 4;
    const int wn4 = (tid & 15) * 4;

    for (int k0 = 0; k0 < H_DIM; k0 += BK) {
#pragma unroll
        for (int i = 0; i < 4; i++) {
            int row = xr + i * 32;
            float4 v = *(const float4*)(g_act + (size_t)(m0 + row) * H_DIM + k0 + xc4);
            As[row][xc4 + 0] = to_tf32(v.x);
            As[row][xc4 + 1] = to_tf32(v.y);
            As[row][xc4 + 2] = to_tf32(v.z);
            As[row][xc4 + 3] = to_tf32(v.w);
        }
#pragma unroll
        for (int i = 0; i < 2; i++) {
            int k = wkr + i * 16;
            float4 v = *(const float4*)(W2 + (size_t)(k0 + k) * D_DIM + n0 + wn4);
            Ws[wn4 + 0][k] = to_tf32(v.x);
            Ws[wn4 + 1][k] = to_tf32(v.y);
            Ws[wn4 + 2][k] = to_tf32(v.z);
            Ws[wn4 + 3][k] = to_tf32(v.w);
        }
        __syncthreads();

        const int ar = lane >> 2, ak = lane & 3;
#pragma unroll
        for (int kk = 0; kk < BK; kk += 8) {
            float a[2][4];
#pragma unroll
            for (int mf = 0; mf < 2; mf++) {
                int rb = wm + mf * 16;
                a[mf][0] = As[rb + ar][kk + ak];
                a[mf][1] = As[rb + ar + 8][kk + ak];
                a[mf][2] = As[rb + ar][kk + ak + 4];
                a[mf][3] = As[rb + ar + 8][kk + ak + 4];
            }
#pragma unroll
            for (int nf = 0; nf < 4; nf++) {
                int nb = wn + nf * 8 + (lane >> 2);
                float b[2] = { Ws[nb][kk + (lane & 3)], Ws[nb][kk + 4 + (lane & 3)] };
#pragma unroll
                for (int mf = 0; mf < 2; mf++) mma_tf32(acc[mf][nf], a[mf], b);
            }
        }
        __syncthreads();
    }

    // epilogue
#pragma unroll
    for (int mf = 0; mf < 2; mf++) {
        int row0 = m0 + wm + mf * 16 + (lane >> 2);
        int row1 = row0 + 8;
        float s0, s1;
        if (expert < 0) { s0 = 1.f; s1 = 1.f; }
        else {
            s0 = g_w[(size_t)expert * T_TOK + row0];
            s1 = g_w[(size_t)expert * T_TOK + row1];
        }
#pragma unroll
        for (int nf = 0; nf < 4; nf++) {
            int col = n0 + wn + nf * 8 + (lane & 3) * 2;
            float2* p0 = (float2*)(out + (size_t)row0 * D_DIM + col);
            float2* p1 = (float2*)(out + (size_t)row1 * D_DIM + col);
            if (expert < 0) {
                float2 v0 = { acc[mf][nf][0], acc[mf][nf][1] };
                float2 v1 = { acc[mf][nf][2], acc[mf][nf][3] };
                *p0 = v0;
                *p1 = v1;
            } else {
                if (s0 != 0.f) {
                    float2 v = *p0;
                    v.x += s0 * acc[mf][nf][0];
                    v.y += s0 * acc[mf][nf][1];
                    *p0 = v;
                }
                if (s1 != 0.f) {
                    float2 v = *p1;
                    v.x += s1 * acc[mf][nf][2];
                    v.y += s1 * acc[mf][nf][3];
                    *p1 = v;
                }
            }
        }
    }
}

// ============================================================================
// launcher
// ============================================================================
extern "C" void kernel_launch(void* const* d_in, const int* in_sizes, int n_in,
                              void* d_out, int out_size) {
    const float* x    = (const float*)d_in[0];
    const float* W1   = (const float*)d_in[1];
    const float* Wg   = (const float*)d_in[2];
    const float* W2   = (const float*)d_in[3];
    const float* Ws1  = (const float*)d_in[4];
    const float* Wsg  = (const float*)d_in[5];
    const float* Ws2  = (const float*)d_in[6];
    const float* gw   = (const float*)d_in[7];
    const float* gb   = (const float*)d_in[8];
    const float* bias = (const float*)d_in[9];
    float* out = (float*)d_out;

    (void)in_sizes; (void)n_in; (void)out_size;

    // 1) routing weights
    gate_kernel<<<T_TOK, 128>>>(x, gw, gb, bias);

    dim3 grid(T_TOK / BM, H_DIM / BN);   // H_DIM == D_DIM so same grid for both GEMMs

    // 2) shared expert: out = ffn_shared(x)
    gemm1_swiglu<<<grid, 256>>>(x, Ws1, Wsg);
    gemm2_combine<<<grid, 256>>>(Ws2, out, -1);

    // 3) routed experts (dense-masked): out += w_e * ffn_e(x)
    for (int e = 0; e < NEXP; e++) {
        const float* w1p = W1 + (size_t)e * D_DIM * H_DIM;
        const float* wgp = Wg + (size_t)e * D_DIM * H_DIM;
        const float* w2p = W2 + (size_t)e * H_DIM * D_DIM;
        gemm1_swiglu<<<grid, 256>>>(x, w1p, wgp);
        gemm2_combine<<<grid, 256>>>(w2p, out, e);
    }
}

// round 2
// speedup vs baseline: 5.1406x; 5.1406x over previous
#include <cuda_runtime.h>
#include <cstdint>

// ---------------- problem constants ----------------
#define T_TOK 8192
#define D_DIM 2048
#define H_DIM 2048
#define NEXP  7
#define TOPK  3

// ---------------- tiling ----------------
#define BM 128
#define BN 128
#define BK 32
#define NTHREADS 256
#define XSTRIDE 36            // floats per A-row in smem (16B aligned, conflict-free)
#define WSTRIDE 136           // floats per B k-row in smem (16B aligned, conflict-free)
#define NIT (D_DIM / BK)      // 64 k-iterations (D_DIM == H_DIM)

#define ST1 (128 * XSTRIDE + 2 * 32 * WSTRIDE)   // gemm1 stage floats = 13312
#define ST2 (128 * XSTRIDE + 32 * WSTRIDE)       // gemm2 stage floats = 8960
#define SMEM1_BYTES (2 * ST1 * 4)                // 106496
#define SMEM2_BYTES (2 * ST2 * 4)                // 71680

// ---------------- device scratch (no allocations allowed) ----------------
__device__ int   g_cnt[NEXP];
__device__ int   g_idx[NEXP][T_TOK];             // token id per (expert, position)
__device__ int   g_te[T_TOK][TOPK];              // expert ids per token
__device__ int   g_tp[T_TOK][TOPK];              // positions per token
__device__ float g_tw[T_TOK][TOPK];              // combine weights per token
__device__ float g_act[8][(size_t)T_TOK * H_DIM];  // SwiGLU acts per expert slot (z=7 shared)
__device__ float g_y[NEXP][(size_t)T_TOK * D_DIM]; // staged routed outputs (positional rows)

// ---------------- helpers ----------------
__device__ __forceinline__ float to_tf32(float x) {
    float r;
    asm("cvt.rna.tf32.f32 %0, %1;" : "=f"(r) : "f"(x));
    return r;
}

__device__ __forceinline__ float silu_f(float z) {
    return z / (1.0f + __expf(-z));
}

__device__ __forceinline__ void mma_tf32(float c[4], const float a[4], const float b[2]) {
    asm volatile(
        "mma.sync.aligned.m16n8k8.row.col.f32.tf32.tf32.f32 "
        "{%0,%1,%2,%3}, {%4,%5,%6,%7}, {%8,%9}, {%0,%1,%2,%3};\n"
        : "+f"(c[0]), "+f"(c[1]), "+f"(c[2]), "+f"(c[3])
        : "r"(__float_as_uint(a[0])), "r"(__float_as_uint(a[1])),
          "r"(__float_as_uint(a[2])), "r"(__float_as_uint(a[3])),
          "r"(__float_as_uint(b[0])), "r"(__float_as_uint(b[1])));
}

__device__ __forceinline__ void cpa16(uint32_t saddr, const void* gptr) {
    asm volatile("cp.async.cg.shared.global [%0], [%1], 16;\n" :: "r"(saddr), "l"(gptr));
}
__device__ __forceinline__ void cpa_commit() {
    asm volatile("cp.async.commit_group;\n" ::: "memory");
}
__device__ __forceinline__ void cpa_wait1() {
    asm volatile("cp.async.wait_group 1;\n" ::: "memory");
}
__device__ __forceinline__ void cpa_wait0() {
    asm volatile("cp.async.wait_group 0;\n" ::: "memory");
}

// ============================================================================
// zero routing counters
// ============================================================================
__global__ void zero_cnt() {
    if (threadIdx.x < NEXP) g_cnt[threadIdx.x] = 0;
}

// ============================================================================
// gate: logits -> softmax -> biased top-3 -> normalized weights + compact lists
// one block (128 threads) per token
// ============================================================================
__global__ void gate_kernel(const float* __restrict__ x,
                            const float* __restrict__ gw,
                            const float* __restrict__ gb,
                            const float* __restrict__ biases) {
    const int t = blockIdx.x;
    const float* xr = x + (size_t)t * D_DIM;

    float p[NEXP];
#pragma unroll
    for (int e = 0; e < NEXP; e++) p[e] = 0.f;

    for (int i = threadIdx.x; i < D_DIM; i += 128) {
        float xv = xr[i];
        const float* g = gw + (size_t)i * NEXP;
#pragma unroll
        for (int e = 0; e < NEXP; e++) p[e] += xv * g[e];
    }
#pragma unroll
    for (int off = 16; off > 0; off >>= 1) {
#pragma unroll
        for (int e = 0; e < NEXP; e++)
            p[e] += __shfl_xor_sync(0xffffffffu, p[e], off);
    }

    __shared__ float sm[4][NEXP];
    const int wid = threadIdx.x >> 5, lane = threadIdx.x & 31;
    if (lane == 0) {
#pragma unroll
        for (int e = 0; e < NEXP; e++) sm[wid][e] = p[e];
    }
    __syncthreads();

    if (threadIdx.x == 0) {
        float logit[NEXP];
#pragma unroll
        for (int e = 0; e < NEXP; e++)
            logit[e] = sm[0][e] + sm[1][e] + sm[2][e] + sm[3][e] + gb[e];

        float mx = logit[0];
#pragma unroll
        for (int e = 1; e < NEXP; e++) mx = fmaxf(mx, logit[e]);
        float pr[NEXP], den = 0.f;
#pragma unroll
        for (int e = 0; e < NEXP; e++) { pr[e] = __expf(logit[e] - mx); den += pr[e]; }
#pragma unroll
        for (int e = 0; e < NEXP; e++) pr[e] /= den;

        float bi[NEXP];
#pragma unroll
        for (int e = 0; e < NEXP; e++) bi[e] = pr[e] + biases[e];

        bool used[NEXP] = {false, false, false, false, false, false, false};
        int sel[TOPK];
#pragma unroll
        for (int k = 0; k < TOPK; k++) {
            int best = -1; float bv = -1e30f;
#pragma unroll
            for (int e = 0; e < NEXP; e++)
                if (!used[e] && bi[e] > bv) { bv = bi[e]; best = e; }
            used[best] = true; sel[k] = best;
        }
        float ws = pr[sel[0]] + pr[sel[1]] + pr[sel[2]];

#pragma unroll
        for (int k = 0; k < TOPK; k++) {
            int e = sel[k];
            float w = pr[e] / ws;
            int pos = atomicAdd(&g_cnt[e], 1);
            g_idx[e][pos] = t;
            g_te[t][k] = e;
            g_tp[t][k] = pos;
            g_tw[t][k] = w;
        }
    }
}

// ============================================================================
// GEMM1 (all experts): act[z] = silu(Xg @ W1[z]) * (Xg @ Wg[z])
// z = 0..6 routed (gathered rows), z = 7 shared (identity rows).
// Block 128x128, BK=32, 8 warps (2m x 4n), warp tile 64x32, tf32 mma,
// cp.async double-buffered. A smem [m][k] stride 36; B smem [k][n] stride 136.
// ============================================================================
__global__ void __launch_bounds__(NTHREADS, 1)
gemm1_all(const float* __restrict__ X,
          const float* __restrict__ W1, const float* __restrict__ Wg,
          const float* __restrict__ Ws1, const float* __restrict__ Wsg) {
    extern __shared__ float smem[];
    const int z = blockIdx.z;

    const float *B1p, *Bgp;
    int cnt;
    const int* idxp;
    if (z < NEXP) {
        B1p = W1 + (size_t)z * D_DIM * H_DIM;
        Bgp = Wg + (size_t)z * D_DIM * H_DIM;
        cnt = g_cnt[z];
        idxp = g_idx[z];
    } else {
        B1p = Ws1; Bgp = Wsg; cnt = T_TOK; idxp = nullptr;
    }

    const int m0 = blockIdx.x * BM;
    if (m0 >= cnt) return;
    const int n0 = blockIdx.y * BN;
    const int tid = threadIdx.x;

    // gather token rows for this thread's 4 X-load rows
    int trow[4];
#pragma unroll
    for (int i = 0; i < 4; i++) {
        int r = m0 + ((tid + i * NTHREADS) >> 3);
        int t;
        if (idxp) t = (r < cnt) ? idxp[r] : 0;
        else      t = r;
        trow[i] = t;
    }

    auto load_stage = [&](int s, int k0) {
        float* xb = smem + s * ST1;
        float* b1 = xb + 128 * XSTRIDE;
        float* bg = b1 + 32 * WSTRIDE;
#pragma unroll
        for (int i = 0; i < 4; i++) {
            int c = tid + i * NTHREADS;
            int r = c >> 3, c4 = (c & 7) * 4;
            cpa16((uint32_t)__cvta_generic_to_shared(xb + r * XSTRIDE + c4),
                  X + (size_t)trow[i] * D_DIM + k0 + c4);
        }
#pragma unroll
        for (int i = 0; i < 4; i++) {
            int c = tid + i * NTHREADS;
            int kr = c >> 5, nn = (c & 31) * 4;
            cpa16((uint32_t)__cvta_generic_to_shared(b1 + kr * WSTRIDE + nn),
                  B1p + (size_t)(k0 + kr) * H_DIM + n0 + nn);
            cpa16((uint32_t)__cvta_generic_to_shared(bg + kr * WSTRIDE + nn),
                  Bgp + (size_t)(k0 + kr) * H_DIM + n0 + nn);
        }
        cpa_commit();
    };

    float acc1[4][4][4];
    float accg[4][4][4];
#pragma unroll
    for (int i = 0; i < 4; i++)
#pragma unroll
        for (int j = 0; j < 4; j++)
#pragma unroll
            for (int r = 0; r < 4; r++) { acc1[i][j][r] = 0.f; accg[i][j][r] = 0.f; }

    const int wid = tid >> 5, lane = tid & 31;
    const int wm = (wid & 1) * 64, wn = (wid >> 1) * 32;
    const int qr = lane >> 2, qk = lane & 3;

    load_stage(0, 0);
    for (int it = 0; it < NIT; ++it) {
        if (it + 1 < NIT) { load_stage((it + 1) & 1, (it + 1) * BK); cpa_wait1(); }
        else              { cpa_wait0(); }
        __syncthreads();

        const float* xb = smem + (it & 1) * ST1;
        const float* b1 = xb + 128 * XSTRIDE;
        const float* bg = b1 + 32 * WSTRIDE;

#pragma unroll
        for (int kk = 0; kk < BK; kk += 8) {
            float a[4][4];
#pragma unroll
            for (int mf = 0; mf < 4; mf++) {
                int r = wm + mf * 16 + qr;
                a[mf][0] = to_tf32(xb[r * XSTRIDE + kk + qk]);
                a[mf][1] = to_tf32(xb[(r + 8) * XSTRIDE + kk + qk]);
                a[mf][2] = to_tf32(xb[r * XSTRIDE + kk + qk + 4]);
                a[mf][3] = to_tf32(xb[(r + 8) * XSTRIDE + kk + qk + 4]);
            }
#pragma unroll
            for (int nf = 0; nf < 4; nf++) {
                int n = wn + nf * 8 + qr;
                float f1[2] = { to_tf32(b1[(kk + qk) * WSTRIDE + n]),
                                to_tf32(b1[(kk + qk + 4) * WSTRIDE + n]) };
                float fg[2] = { to_tf32(bg[(kk + qk) * WSTRIDE + n]),
                                to_tf32(bg[(kk + qk + 4) * WSTRIDE + n]) };
#pragma unroll
                for (int mf = 0; mf < 4; mf++) {
                    mma_tf32(acc1[mf][nf], a[mf], f1);
                    mma_tf32(accg[mf][nf], a[mf], fg);
                }
            }
        }
        __syncthreads();
    }

    // epilogue: silu(acc1)*accg -> g_act[z] (positional rows)
    float* actp = g_act[z];
#pragma unroll
    for (int mf = 0; mf < 4; mf++) {
        int r0 = m0 + wm + mf * 16 + qr;
        int r1 = r0 + 8;
#pragma unroll
        for (int nf = 0; nf < 4; nf++) {
            int cl = n0 + wn + nf * 8 + qk * 2;
            float2 v0, v1;
            v0.x = silu_f(acc1[mf][nf][0]) * accg[mf][nf][0];
            v0.y = silu_f(acc1[mf][nf][1]) * accg[mf][nf][1];
            v1.x = silu_f(acc1[mf][nf][2]) * accg[mf][nf][2];
            v1.y = silu_f(acc1[mf][nf][3]) * accg[mf][nf][3];
            *(float2*)(actp + (size_t)r0 * H_DIM + cl) = v0;
            *(float2*)(actp + (size_t)r1 * H_DIM + cl) = v1;
        }
    }
}

// ============================================================================
// GEMM2 (all experts): y = act[z] @ W2[z]
// z < 7 -> staged g_y[z] (positional rows, skip pads); z = 7 -> out directly.
// ============================================================================
__global__ void __launch_bounds__(NTHREADS, 1)
gemm2_all(const float* __restrict__ W2, const float* __restrict__ Ws2,
          float* __restrict__ out) {
    extern __shared__ float smem[];
    const int z = blockIdx.z;

    const float* Bp;
    int cnt;
    if (z < NEXP) { Bp = W2 + (size_t)z * H_DIM * D_DIM; cnt = g_cnt[z]; }
    else          { Bp = Ws2; cnt = T_TOK; }
    const float* Ap = g_act[z];

    const int m0 = blockIdx.x * BM;
    if (m0 >= cnt) return;
    const int n0 = blockIdx.y * BN;
    const int tid = threadIdx.x;

    auto load_stage = [&](int s, int k0) {
        float* ab = smem + s * ST2;
        float* bb = ab + 128 * XSTRIDE;
#pragma unroll
        for (int i = 0; i < 4; i++) {
            int c = tid + i * NTHREADS;
            int r = c >> 3, c4 = (c & 7) * 4;
            cpa16((uint32_t)__cvta_generic_to_shared(ab + r * XSTRIDE + c4),
                  Ap + (size_t)(m0 + r) * H_DIM + k0 + c4);
        }
#pragma unroll
        for (int i = 0; i < 4; i++) {
            int c = tid + i * NTHREADS;
            int kr = c >> 5, nn = (c & 31) * 4;
            cpa16((uint32_t)__cvta_generic_to_shared(bb + kr * WSTRIDE + nn),
                  Bp + (size_t)(k0 + kr) * D_DIM + n0 + nn);
        }
        cpa_commit();
    };

    float acc[4][4][4];
#pragma unroll
    for (int i = 0; i < 4; i++)
#pragma unroll
        for (int j = 0; j < 4; j++)
#pragma unroll
            for (int r = 0; r < 4; r++) acc[i][j][r] = 0.f;

    const int wid = tid >> 5, lane = tid & 31;
    const int wm = (wid & 1) * 64, wn = (wid >> 1) * 32;
    const int qr = lane >> 2, qk = lane & 3;

    load_stage(0, 0);
    for (int it = 0; it < NIT; ++it) {
        if (it + 1 < NIT) { load_stage((it + 1) & 1, (it + 1) * BK); cpa_wait1(); }
        else              { cpa_wait0(); }
        __syncthreads();

        const float* ab = smem + (it & 1) * ST2;
        const float* bb = ab + 128 * XSTRIDE;

#pragma unroll
        for (int kk = 0; kk < BK; kk += 8) {
            float a[4][4];
#pragma unroll
            for (int mf = 0; mf < 4; mf++) {
                int r = wm + mf * 16 + qr;
                a[mf][0] = to_tf32(ab[r * XSTRIDE + kk + qk]);
                a[mf][1] = to_tf32(ab[(r + 8) * XSTRIDE + kk + qk]);
                a[mf][2] = to_tf32(ab[r * XSTRIDE + kk + qk + 4]);
                a[mf][3] = to_tf32(ab[(r + 8) * XSTRIDE + kk + qk + 4]);
            }
#pragma unroll
            for (int nf = 0; nf < 4; nf++) {
                int n = wn + nf * 8 + qr;
                float b[2] = { to_tf32(bb[(kk + qk) * WSTRIDE + n]),
                               to_tf32(bb[(kk + qk + 4) * WSTRIDE + n]) };
#pragma unroll
                for (int mf = 0; mf < 4; mf++) mma_tf32(acc[mf][nf], a[mf], b);
            }
        }
        __syncthreads();
    }

    // epilogue
#pragma unroll
    for (int mf = 0; mf < 4; mf++) {
        int r0 = m0 + wm + mf * 16 + qr;
        int r1 = r0 + 8;
#pragma unroll
        for (int nf = 0; nf < 4; nf++) {
            int cl = n0 + wn + nf * 8 + qk * 2;
            float2 v0 = { acc[mf][nf][0], acc[mf][nf][1] };
            float2 v1 = { acc[mf][nf][2], acc[mf][nf][3] };
            if (z == NEXP) {   // shared expert: rows are token ids, write out
                *(float2*)(out + (size_t)r0 * D_DIM + cl) = v0;
                *(float2*)(out + (size_t)r1 * D_DIM + cl) = v1;
            } else {
                float* yp = g_y[z];
                if (r0 < cnt) *(float2*)(yp + (size_t)r0 * D_DIM + cl) = v0;
                if (r1 < cnt) *(float2*)(yp + (size_t)r1 * D_DIM + cl) = v1;
            }
        }
    }
}

// ============================================================================
// combine: out[t] += sum_k w_k * y[e_k][pos_k]   (deterministic, no atomics)
// ============================================================================
__global__ void combine_kernel(float* __restrict__ out) {
    const int t = blockIdx.x;
    const int e0 = g_te[t][0], e1 = g_te[t][1], e2 = g_te[t][2];
    const float w0 = g_tw[t][0], w1 = g_tw[t][1], w2 = g_tw[t][2];
    const float4* y0 = (const float4*)(g_y[e0] + (size_t)g_tp[t][0] * D_DIM);
    const float4* y1 = (const float4*)(g_y[e1] + (size_t)g_tp[t][1] * D_DIM);
    const float4* y2 = (const float4*)(g_y[e2] + (size_t)g_tp[t][2] * D_DIM);
    float4* o = (float4*)(out + (size_t)t * D_DIM);

    for (int i = threadIdx.x; i < D_DIM / 4; i += 256) {
        float4 v = o[i];
        float4 a = y0[i], b = y1[i], c = y2[i];
        v.x += w0 * a.x + w1 * b.x + w2 * c.x;
        v.y += w0 * a.y + w1 * b.y + w2 * c.y;
        v.z += w0 * a.z + w1 * b.z + w2 * c.z;
        v.w += w0 * a.w + w1 * b.w + w2 * c.w;
        o[i] = v;
    }
}

// ============================================================================
// launcher
// ============================================================================
extern "C" void kernel_launch(void* const* d_in, const int* in_sizes, int n_in,
                              void* d_out, int out_size) {
    const float* x    = (const float*)d_in[0];
    const float* W1   = (const float*)d_in[1];
    const float* Wg   = (const float*)d_in[2];
    const float* W2   = (const float*)d_in[3];
    const float* Ws1  = (const float*)d_in[4];
    const float* Wsg  = (const float*)d_in[5];
    const float* Ws2  = (const float*)d_in[6];
    const float* gw   = (const float*)d_in[7];
    const float* gb   = (const float*)d_in[8];
    const float* bias = (const float*)d_in[9];
    float* out = (float*)d_out;
    (void)in_sizes; (void)n_in; (void)out_size;

    cudaFuncSetAttribute(gemm1_all, cudaFuncAttributeMaxDynamicSharedMemorySize, SMEM1_BYTES);
    cudaFuncSetAttribute(gemm2_all, cudaFuncAttributeMaxDynamicSharedMemorySize, SMEM2_BYTES);

    zero_cnt<<<1, 32>>>();
    gate_kernel<<<T_TOK, 128>>>(x, gw, gb, bias);
    gemm1_all<<<dim3(T_TOK / BM, H_DIM / BN, 8), NTHREADS, SMEM1_BYTES>>>(x, W1, Wg, Ws1, Wsg);
    gemm2_all<<<dim3(T_TOK / BM, D_DIM / BN, 8), NTHREADS, SMEM2_BYTES>>>(W2, Ws2, out);
    combine_kernel<<<T_TOK, 256>>>(out);
}

// round 3
// speedup vs baseline: 5.1754x; 1.0068x over previous
#include <cuda_runtime.h>
#include <cstdint>

// ---------------- problem constants ----------------
#define T_TOK 8192
#define D_DIM 2048
#define H_DIM 2048
#define NEXP  7
#define TOPK  3

// ---------------- tiling ----------------
#define BM 128
#define BN 128
#define BK 32
#define NTHREADS 256
#define XSTRIDE 36            // floats per A-row in smem (16B aligned, conflict-free)
#define WSTRIDE 136           // floats per B k-row in smem (16B aligned, conflict-free)
#define NIT (D_DIM / BK)      // 64 k-iterations (D_DIM == H_DIM)

#define ST1 (128 * XSTRIDE + 2 * 32 * WSTRIDE)   // gemm1 stage floats = 13312
#define ST2 (128 * XSTRIDE + 32 * WSTRIDE)       // gemm2 stage floats = 8960
#define SMEM1_BYTES (2 * ST1 * 4)                // 106496
#define SMEM2_BYTES (2 * ST2 * 4)                // 71680

#define WELEMS ((size_t)NEXP * D_DIM * H_DIM)    // 29360128
#define SELEMS ((size_t)D_DIM * H_DIM)           // 4194304
#define XELEMS ((size_t)T_TOK * D_DIM)           // 16777216

// ---------------- device scratch (no allocations allowed) ----------------
__device__ int   g_cnt[NEXP];
__device__ int   g_idx[NEXP][T_TOK];             // token id per (expert, position)
__device__ int   g_te[T_TOK][TOPK];              // expert ids per token
__device__ int   g_tp[T_TOK][TOPK];              // positions per token
__device__ float g_tw[T_TOK][TOPK];              // combine weights per token
__device__ float g_act[8][(size_t)T_TOK * H_DIM];  // SwiGLU acts (tf32-rounded)
__device__ float g_y[NEXP][(size_t)T_TOK * D_DIM]; // staged routed outputs

// tf32-rounded operand copies
__device__ float g_w1r[WELEMS];
__device__ float g_wgr[WELEMS];
__device__ float g_w2r[WELEMS];
__device__ float g_ws1r[SELEMS];
__device__ float g_wsgr[SELEMS];
__device__ float g_ws2r[SELEMS];
__device__ float g_xr[XELEMS];

// ---------------- helpers ----------------
__device__ __forceinline__ float to_tf32(float x) {
    float r;
    asm("cvt.rna.tf32.f32 %0, %1;" : "=f"(r) : "f"(x));
    return r;
}

__device__ __forceinline__ float silu_f(float z) {
    return z / (1.0f + __expf(-z));
}

__device__ __forceinline__ void mma_tf32(float c[4], const float a[4], const float b[2]) {
    asm volatile(
        "mma.sync.aligned.m16n8k8.row.col.f32.tf32.tf32.f32 "
        "{%0,%1,%2,%3}, {%4,%5,%6,%7}, {%8,%9}, {%0,%1,%2,%3};\n"
        : "+f"(c[0]), "+f"(c[1]), "+f"(c[2]), "+f"(c[3])
        : "r"(__float_as_uint(a[0])), "r"(__float_as_uint(a[1])),
          "r"(__float_as_uint(a[2])), "r"(__float_as_uint(a[3])),
          "r"(__float_as_uint(b[0])), "r"(__float_as_uint(b[1])));
}

__device__ __forceinline__ void cpa16(uint32_t saddr, const void* gptr) {
    asm volatile("cp.async.cg.shared.global [%0], [%1], 16;\n" :: "r"(saddr), "l"(gptr));
}
__device__ __forceinline__ void cpa_commit() {
    asm volatile("cp.async.commit_group;\n" ::: "memory");
}
__device__ __forceinline__ void cpa_wait1() {
    asm volatile("cp.async.wait_group 1;\n" ::: "memory");
}
__device__ __forceinline__ void cpa_wait0() {
    asm volatile("cp.async.wait_group 0;\n" ::: "memory");
}

// ============================================================================
// tf32 pre-rounding pass (float4 vectorized, grid-stride)
// ============================================================================
__global__ void cvt_kernel(const float* __restrict__ src, float* __restrict__ dst,
                           int n4) {
    for (int i = blockIdx.x * blockDim.x + threadIdx.x; i < n4;
         i += gridDim.x * blockDim.x) {
        float4 v = ((const float4*)src)[i];
        v.x = to_tf32(v.x);
        v.y = to_tf32(v.y);
        v.z = to_tf32(v.z);
        v.w = to_tf32(v.w);
        ((float4*)dst)[i] = v;
    }
}

// ============================================================================
// zero routing counters
// ============================================================================
__global__ void zero_cnt() {
    if (threadIdx.x < NEXP) g_cnt[threadIdx.x] = 0;
}

// ============================================================================
// gate: logits -> softmax -> biased top-3 -> normalized weights + compact lists
// ============================================================================
__global__ void gate_kernel(const float* __restrict__ x,
                            const float* __restrict__ gw,
                            const float* __restrict__ gb,
                            const float* __restrict__ biases) {
    const int t = blockIdx.x;
    const float* xr = x + (size_t)t * D_DIM;

    float p[NEXP];
#pragma unroll
    for (int e = 0; e < NEXP; e++) p[e] = 0.f;

    for (int i = threadIdx.x; i < D_DIM; i += 128) {
        float xv = xr[i];
        const float* g = gw + (size_t)i * NEXP;
#pragma unroll
        for (int e = 0; e < NEXP; e++) p[e] += xv * g[e];
    }
#pragma unroll
    for (int off = 16; off > 0; off >>= 1) {
#pragma unroll
        for (int e = 0; e < NEXP; e++)
            p[e] += __shfl_xor_sync(0xffffffffu, p[e], off);
    }

    __shared__ float sm[4][NEXP];
    const int wid = threadIdx.x >> 5, lane = threadIdx.x & 31;
    if (lane == 0) {
#pragma unroll
        for (int e = 0; e < NEXP; e++) sm[wid][e] = p[e];
    }
    __syncthreads();

    if (threadIdx.x == 0) {
        float logit[NEXP];
#pragma unroll
        for (int e = 0; e < NEXP; e++)
            logit[e] = sm[0][e] + sm[1][e] + sm[2][e] + sm[3][e] + gb[e];

        float mx = logit[0];
#pragma unroll
        for (int e = 1; e < NEXP; e++) mx = fmaxf(mx, logit[e]);
        float pr[NEXP], den = 0.f;
#pragma unroll
        for (int e = 0; e < NEXP; e++) { pr[e] = __expf(logit[e] - mx); den += pr[e]; }
#pragma unroll
        for (int e = 0; e < NEXP; e++) pr[e] /= den;

        float bi[NEXP];
#pragma unroll
        for (int e = 0; e < NEXP; e++) bi[e] = pr[e] + biases[e];

        bool used[NEXP] = {false, false, false, false, false, false, false};
        int sel[TOPK];
#pragma unroll
        for (int k = 0; k < TOPK; k++) {
            int best = -1; float bv = -1e30f;
#pragma unroll
            for (int e = 0; e < NEXP; e++)
                if (!used[e] && bi[e] > bv) { bv = bi[e]; best = e; }
            used[best] = true; sel[k] = best;
        }
        float ws = pr[sel[0]] + pr[sel[1]] + pr[sel[2]];

#pragma unroll
        for (int k = 0; k < TOPK; k++) {
            int e = sel[k];
            float w = pr[e] / ws;
            int pos = atomicAdd(&g_cnt[e], 1);
            g_idx[e][pos] = t;
            g_te[t][k] = e;
            g_tp[t][k] = pos;
            g_tw[t][k] = w;
        }
    }
}

// ============================================================================
// GEMM1 (all experts): act[z] = silu(Xg @ W1[z]) * (Xg @ Wg[z])
// All operands pre-rounded to tf32 -> no cvt in the mainloop.
// ============================================================================
__global__ void __launch_bounds__(NTHREADS, 1)
gemm1_all() {
    extern __shared__ float smem[];
    const int z = blockIdx.z;

    const float *B1p, *Bgp;
    int cnt;
    const int* idxp;
    if (z < NEXP) {
        B1p = g_w1r + (size_t)z * D_DIM * H_DIM;
        Bgp = g_wgr + (size_t)z * D_DIM * H_DIM;
        cnt = g_cnt[z];
        idxp = g_idx[z];
    } else {
        B1p = g_ws1r; Bgp = g_wsgr; cnt = T_TOK; idxp = nullptr;
    }

    const int m0 = blockIdx.x * BM;
    if (m0 >= cnt) return;
    const int n0 = blockIdx.y * BN;
    const int tid = threadIdx.x;

    int trow[4];
#pragma unroll
    for (int i = 0; i < 4; i++) {
        int r = m0 + ((tid + i * NTHREADS) >> 3);
        int t;
        if (idxp) t = (r < cnt) ? idxp[r] : 0;
        else      t = r;
        trow[i] = t;
    }

    auto load_stage = [&](int s, int k0) {
        float* xb = smem + s * ST1;
        float* b1 = xb + 128 * XSTRIDE;
        float* bg = b1 + 32 * WSTRIDE;
#pragma unroll
        for (int i = 0; i < 4; i++) {
            int c = tid + i * NTHREADS;
            int r = c >> 3, c4 = (c & 7) * 4;
            cpa16((uint32_t)__cvta_generic_to_shared(xb + r * XSTRIDE + c4),
                  g_xr + (size_t)trow[i] * D_DIM + k0 + c4);
        }
#pragma unroll
        for (int i = 0; i < 4; i++) {
            int c = tid + i * NTHREADS;
            int kr = c >> 5, nn = (c & 31) * 4;
            cpa16((uint32_t)__cvta_generic_to_shared(b1 + kr * WSTRIDE + nn),
                  B1p + (size_t)(k0 + kr) * H_DIM + n0 + nn);
            cpa16((uint32_t)__cvta_generic_to_shared(bg + kr * WSTRIDE + nn),
                  Bgp + (size_t)(k0 + kr) * H_DIM + n0 + nn);
        }
        cpa_commit();
    };

    float acc1[4][4][4];
    float accg[4][4][4];
#pragma unroll
    for (int i = 0; i < 4; i++)
#pragma unroll
        for (int j = 0; j < 4; j++)
#pragma unroll
            for (int r = 0; r < 4; r++) { acc1[i][j][r] = 0.f; accg[i][j][r] = 0.f; }

    const int wid = tid >> 5, lane = tid & 31;
    const int wm = (wid & 1) * 64, wn = (wid >> 1) * 32;
    const int qr = lane >> 2, qk = lane & 3;

    load_stage(0, 0);
    for (int it = 0; it < NIT; ++it) {
        if (it + 1 < NIT) { load_stage((it + 1) & 1, (it + 1) * BK); cpa_wait1(); }
        else              { cpa_wait0(); }
        __syncthreads();

        const float* xb = smem + (it & 1) * ST1;
        const float* b1 = xb + 128 * XSTRIDE;
        const float* bg = b1 + 32 * WSTRIDE;

#pragma unroll
        for (int kk = 0; kk < BK; kk += 8) {
            float a[4][4];
#pragma unroll
            for (int mf = 0; mf < 4; mf++) {
                int r = wm + mf * 16 + qr;
                a[mf][0] = xb[r * XSTRIDE + kk + qk];
                a[mf][1] = xb[(r + 8) * XSTRIDE + kk + qk];
                a[mf][2] = xb[r * XSTRIDE + kk + qk + 4];
                a[mf][3] = xb[(r + 8) * XSTRIDE + kk + qk + 4];
            }
#pragma unroll
            for (int nf = 0; nf < 4; nf++) {
                int n = wn + nf * 8 + qr;
                float f1[2] = { b1[(kk + qk) * WSTRIDE + n], b1[(kk + qk + 4) * WSTRIDE + n] };
                float fg[2] = { bg[(kk + qk) * WSTRIDE + n], bg[(kk + qk + 4) * WSTRIDE + n] };
#pragma unroll
                for (int mf = 0; mf < 4; mf++) {
                    mma_tf32(acc1[mf][nf], a[mf], f1);
                    mma_tf32(accg[mf][nf], a[mf], fg);
                }
            }
        }
        __syncthreads();
    }

    // epilogue: tf32(silu(acc1)*accg) -> g_act[z]
    float* actp = g_act[z];
#pragma unroll
    for (int mf = 0; mf < 4; mf++) {
        int r0 = m0 + wm + mf * 16 + qr;
        int r1 = r0 + 8;
#pragma unroll
        for (int nf = 0; nf < 4; nf++) {
            int cl = n0 + wn + nf * 8 + qk * 2;
            float2 v0, v1;
            v0.x = to_tf32(silu_f(acc1[mf][nf][0]) * accg[mf][nf][0]);
            v0.y = to_tf32(silu_f(acc1[mf][nf][1]) * accg[mf][nf][1]);
            v1.x = to_tf32(silu_f(acc1[mf][nf][2]) * accg[mf][nf][2]);
            v1.y = to_tf32(silu_f(acc1[mf][nf][3]) * accg[mf][nf][3]);
            *(float2*)(actp + (size_t)r0 * H_DIM + cl) = v0;
            *(float2*)(actp + (size_t)r1 * H_DIM + cl) = v1;
        }
    }
}

// ============================================================================
// GEMM2 (all experts): y = act[z] @ W2[z]   (all operands tf32-rounded)
// ============================================================================
__global__ void __launch_bounds__(NTHREADS, 1)
gemm2_all(float* __restrict__ out) {
    extern __shared__ float smem[];
    const int z = blockIdx.z;

    const float* Bp;
    int cnt;
    if (z < NEXP) { Bp = g_w2r + (size_t)z * H_DIM * D_DIM; cnt = g_cnt[z]; }
    else          { Bp = g_ws2r; cnt = T_TOK; }
    const float* Ap = g_act[z];

    const int m0 = blockIdx.x * BM;
    if (m0 >= cnt) return;
    const int n0 = blockIdx.y * BN;
    const int tid = threadIdx.x;

    auto load_stage = [&](int s, int k0) {
        float* ab = smem + s * ST2;
        float* bb = ab + 128 * XSTRIDE;
#pragma unroll
        for (int i = 0; i < 4; i++) {
            int c = tid + i * NTHREADS;
            int r = c >> 3, c4 = (c & 7) * 4;
            cpa16((uint32_t)__cvta_generic_to_shared(ab + r * XSTRIDE + c4),
                  Ap + (size_t)(m0 + r) * H_DIM + k0 + c4);
        }
#pragma unroll
        for (int i = 0; i < 4; i++) {
            int c = tid + i * NTHREADS;
            int kr = c >> 5, nn = (c & 31) * 4;
            cpa16((uint32_t)__cvta_generic_to_shared(bb + kr * WSTRIDE + nn),
                  Bp + (size_t)(k0 + kr) * D_DIM + n0 + nn);
        }
        cpa_commit();
    };

    float acc[4][4][4];
#pragma unroll
    for (int i = 0; i < 4; i++)
#pragma unroll
        for (int j = 0; j < 4; j++)
#pragma unroll
            for (int r = 0; r < 4; r++) acc[i][j][r] = 0.f;

    const int wid = tid >> 5, lane = tid & 31;
    const int wm = (wid & 1) * 64, wn = (wid >> 1) * 32;
    const int qr = lane >> 2, qk = lane & 3;

    load_stage(0, 0);
    for (int it = 0; it < NIT; ++it) {
        if (it + 1 < NIT) { load_stage((it + 1) & 1, (it + 1) * BK); cpa_wait1(); }
        else              { cpa_wait0(); }
        __syncthreads();

        const float* ab = smem + (it & 1) * ST2;
        const float* bb = ab + 128 * XSTRIDE;

#pragma unroll
        for (int kk = 0; kk < BK; kk += 8) {
            float a[4][4];
#pragma unroll
            for (int mf = 0; mf < 4; mf++) {
                int r = wm + mf * 16 + qr;
                a[mf][0] = ab[r * XSTRIDE + kk + qk];
                a[mf][1] = ab[(r + 8) * XSTRIDE + kk + qk];
                a[mf][2] = ab[r * XSTRIDE + kk + qk + 4];
                a[mf][3] = ab[(r + 8) * XSTRIDE + kk + qk + 4];
            }
#pragma unroll
            for (int nf = 0; nf < 4; nf++) {
                int n = wn + nf * 8 + qr;
                float b[2] = { bb[(kk + qk) * WSTRIDE + n], bb[(kk + qk + 4) * WSTRIDE + n] };
#pragma unroll
                for (int mf = 0; mf < 4; mf++) mma_tf32(acc[mf][nf], a[mf], b);
            }
        }
        __syncthreads();
    }

#pragma unroll
    for (int mf = 0; mf < 4; mf++) {
        int r0 = m0 + wm + mf * 16 + qr;
        int r1 = r0 + 8;
#pragma unroll
        for (int nf = 0; nf < 4; nf++) {
            int cl = n0 + wn + nf * 8 + qk * 2;
            float2 v0 = { acc[mf][nf][0], acc[mf][nf][1] };
            float2 v1 = { acc[mf][nf][2], acc[mf][nf][3] };
            if (z == NEXP) {
                *(float2*)(out + (size_t)r0 * D_DIM + cl) = v0;
                *(float2*)(out + (size_t)r1 * D_DIM + cl) = v1;
            } else {
                float* yp = g_y[z];
                if (r0 < cnt) *(float2*)(yp + (size_t)r0 * D_DIM + cl) = v0;
                if (r1 < cnt) *(float2*)(yp + (size_t)r1 * D_DIM + cl) = v1;
            }
        }
    }
}

// ============================================================================
// combine: out[t] += sum_k w_k * y[e_k][pos_k]
// ============================================================================
__global__ void combine_kernel(float* __restrict__ out) {
    const int t = blockIdx.x;
    const int e0 = g_te[t][0], e1 = g_te[t][1], e2 = g_te[t][2];
    const float w0 = g_tw[t][0], w1 = g_tw[t][1], w2 = g_tw[t][2];
    const float4* y0 = (const float4*)(g_y[e0] + (size_t)g_tp[t][0] * D_DIM);
    const float4* y1 = (const float4*)(g_y[e1] + (size_t)g_tp[t][1] * D_DIM);
    const float4* y2 = (const float4*)(g_y[e2] + (size_t)g_tp[t][2] * D_DIM);
    float4* o = (float4*)(out + (size_t)t * D_DIM);

    for (int i = threadIdx.x; i < D_DIM / 4; i += 256) {
        float4 v = o[i];
        float4 a = y0[i], b = y1[i], c = y2[i];
        v.x += w0 * a.x + w1 * b.x + w2 * c.x;
        v.y += w0 * a.y + w1 * b.y + w2 * c.y;
        v.z += w0 * a.z + w1 * b.z + w2 * c.z;
        v.w += w0 * a.w + w1 * b.w + w2 * c.w;
        o[i] = v;
    }
}

// ============================================================================
// launcher
// ============================================================================
extern "C" void kernel_launch(void* const* d_in, const int* in_sizes, int n_in,
                              void* d_out, int out_size) {
    const float* x    = (const float*)d_in[0];
    const float* W1   = (const float*)d_in[1];
    const float* Wg   = (const float*)d_in[2];
    const float* W2   = (const float*)d_in[3];
    const float* Ws1  = (const float*)d_in[4];
    const float* Wsg  = (const float*)d_in[5];
    const float* Ws2  = (const float*)d_in[6];
    const float* gw   = (const float*)d_in[7];
    const float* gb   = (const float*)d_in[8];
    const float* bias = (const float*)d_in[9];
    float* out = (float*)d_out;
    (void)in_sizes; (void)n_in; (void)out_size;

    cudaFuncSetAttribute(gemm1_all, cudaFuncAttributeMaxDynamicSharedMemorySize, SMEM1_BYTES);
    cudaFuncSetAttribute(gemm2_all, cudaFuncAttributeMaxDynamicSharedMemorySize, SMEM2_BYTES);

    // resolve device-global scratch addresses (host side, no allocation)
    float *w1r, *wgr, *w2r, *ws1r, *wsgr, *ws2r, *xr;
    cudaGetSymbolAddress((void**)&w1r,  g_w1r);
    cudaGetSymbolAddress((void**)&wgr,  g_wgr);
    cudaGetSymbolAddress((void**)&w2r,  g_w2r);
    cudaGetSymbolAddress((void**)&ws1r, g_ws1r);
    cudaGetSymbolAddress((void**)&wsgr, g_wsgr);
    cudaGetSymbolAddress((void**)&ws2r, g_ws2r);
    cudaGetSymbolAddress((void**)&xr,   g_xr);

    // tf32 pre-rounding passes
    cvt_kernel<<<4096, 256>>>(W1,  w1r,  (int)(WELEMS / 4));
    cvt_kernel<<<4096, 256>>>(Wg,  wgr,  (int)(WELEMS / 4));
    cvt_kernel<<<4096, 256>>>(W2,  w2r,  (int)(WELEMS / 4));
    cvt_kernel<<<1024, 256>>>(Ws1, ws1r, (int)(SELEMS / 4));
    cvt_kernel<<<1024, 256>>>(Wsg, wsgr, (int)(SELEMS / 4));
    cvt_kernel<<<1024, 256>>>(Ws2, ws2r, (int)(SELEMS / 4));
    cvt_kernel<<<2048, 256>>>(x,   xr,   (int)(XELEMS / 4));

    zero_cnt<<<1, 32>>>();
    gate_kernel<<<T_TOK, 128>>>(x, gw, gb, bias);
    gemm1_all<<<dim3(T_TOK / BM, H_DIM / BN, 8), NTHREADS, SMEM1_BYTES>>>();
    gemm2_all<<<dim3(T_TOK / BM, D_DIM / BN, 8), NTHREADS, SMEM2_BYTES>>>(out);
    combine_kernel<<<T_TOK, 256>>>(out);
}

// round 4
// speedup vs baseline: 9.2393x; 1.7852x over previous
#include <cuda_runtime.h>
#include <cuda_fp16.h>
#include <cstdint>

// ---------------- problem constants ----------------
#define T_TOK 8192
#define D_DIM 2048
#define H_DIM 2048
#define NEXP  7
#define TOPK  3

// ---------------- tiling ----------------
#define BM 128
#define BN 128
#define BKH 64                 // K-chunk in halfs (128B per row)
#define NTHREADS 256
#define XSTRH 72               // halfs per smem row (padded; conflict-free frag reads)
#define XSTRW 36               // words per smem row
#define NIT (D_DIM / BKH)      // 32 k-iterations

#define TILEH (128 * XSTRH)            // halfs per 128-row tile = 9216
#define ST1H (3 * TILEH)               // gemm1 stage halfs (A + B1 + Bg) = 27648
#define ST2H (2 * TILEH)               // gemm2 stage halfs (A + B) = 18432
#define SMEM1_BYTES (2 * ST1H * 2)     // 110592
#define SMEM2_BYTES (2 * ST2H * 2)     // 73728

#define WELEMS ((size_t)NEXP * D_DIM * H_DIM)
#define SELEMS ((size_t)D_DIM * H_DIM)
#define XELEMS ((size_t)T_TOK * D_DIM)

// ---------------- device scratch (no allocations allowed) ----------------
__device__ int   g_cnt[NEXP];
__device__ __align__(16) int   g_idx[NEXP][T_TOK];
__device__ int   g_te[T_TOK][TOPK];
__device__ int   g_tp[T_TOK][TOPK];
__device__ float g_tw[T_TOK][TOPK];

__device__ __align__(16) __half g_acth[8][(size_t)T_TOK * H_DIM];   // fp16 SwiGLU acts
__device__ __align__(16) float  g_y[NEXP][(size_t)T_TOK * D_DIM];   // staged routed outputs

// fp16 operands: weights TRANSPOSED to [n][k]; x row-major [m][k]
__device__ __align__(16) __half g_w1h[WELEMS];
__device__ __align__(16) __half g_wgh[WELEMS];
__device__ __align__(16) __half g_w2h[WELEMS];
__device__ __align__(16) __half g_ws1h[SELEMS];
__device__ __align__(16) __half g_wsgh[SELEMS];
__device__ __align__(16) __half g_ws2h[SELEMS];
__device__ __align__(16) __half g_xh[XELEMS];

// ---------------- helpers ----------------
__device__ __forceinline__ float silu_f(float z) {
    return z / (1.0f + __expf(-z));
}

__device__ __forceinline__ void mma_f16(float c[4], const uint32_t a[4],
                                        const uint32_t b0, const uint32_t b1) {
    asm volatile(
        "mma.sync.aligned.m16n8k16.row.col.f32.f16.f16.f32 "
        "{%0,%1,%2,%3}, {%4,%5,%6,%7}, {%8,%9}, {%0,%1,%2,%3};\n"
        : "+f"(c[0]), "+f"(c[1]), "+f"(c[2]), "+f"(c[3])
        : "r"(a[0]), "r"(a[1]), "r"(a[2]), "r"(a[3]),
          "r"(b0), "r"(b1));
}

__device__ __forceinline__ void cpa16(uint32_t saddr, const void* gptr) {
    asm volatile("cp.async.cg.shared.global [%0], [%1], 16;\n" :: "r"(saddr), "l"(gptr));
}
__device__ __forceinline__ void cpa_commit() {
    asm volatile("cp.async.commit_group;\n" ::: "memory");
}
__device__ __forceinline__ void cpa_wait1() {
    asm volatile("cp.async.wait_group 1;\n" ::: "memory");
}
__device__ __forceinline__ void cpa_wait0() {
    asm volatile("cp.async.wait_group 0;\n" ::: "memory");
}

// ============================================================================
// weight convert + transpose: src f32 [K=2048][N=2048] -> dst fp16 [N][K]
// grid (32 k-tiles, 64 n-tiles, nmat), block (32, 8)
// ============================================================================
__global__ void cvtT_kernel(const float* __restrict__ src, __half* __restrict__ dst) {
    __shared__ float sm[64][33];
    const size_t moff = (size_t)blockIdx.z * 2048 * 2048;
    const int k0 = blockIdx.x * 64;
    const int n0 = blockIdx.y * 32;
    const int tx = threadIdx.x, ty = threadIdx.y;

#pragma unroll
    for (int i = 0; i < 8; i++) {
        int ky = ty + i * 8;
        sm[ky][tx] = src[moff + (size_t)(k0 + ky) * 2048 + n0 + tx];
    }
    __syncthreads();

#pragma unroll
    for (int j = 0; j < 4; j++) {
        int ny = ty + j * 8;
        __half* drow = dst + moff + (size_t)(n0 + ny) * 2048 + k0;
        drow[tx]      = __float2half(sm[tx][ny]);
        drow[tx + 32] = __float2half(sm[tx + 32][ny]);
    }
}

// ============================================================================
// x convert: f32 -> fp16 (row-major, no transpose)
// ============================================================================
__global__ void cvtX_kernel(const float* __restrict__ src, __half* __restrict__ dst,
                            int n2) {
    for (int i = blockIdx.x * blockDim.x + threadIdx.x; i < n2;
         i += gridDim.x * blockDim.x) {
        float2 v = ((const float2*)src)[i];
        ((__half2*)dst)[i] = __floats2half2_rn(v.x, v.y);
    }
}

// ============================================================================
// zero routing counters
// ============================================================================
__global__ void zero_cnt() {
    if (threadIdx.x < NEXP) g_cnt[threadIdx.x] = 0;
}

// ============================================================================
// gate (fp32, unchanged)
// ============================================================================
__global__ void gate_kernel(const float* __restrict__ x,
                            const float* __restrict__ gw,
                            const float* __restrict__ gb,
                            const float* __restrict__ biases) {
    const int t = blockIdx.x;
    const float* xr = x + (size_t)t * D_DIM;

    float p[NEXP];
#pragma unroll
    for (int e = 0; e < NEXP; e++) p[e] = 0.f;

    for (int i = threadIdx.x; i < D_DIM; i += 128) {
        float xv = xr[i];
        const float* g = gw + (size_t)i * NEXP;
#pragma unroll
        for (int e = 0; e < NEXP; e++) p[e] += xv * g[e];
    }
#pragma unroll
    for (int off = 16; off > 0; off >>= 1) {
#pragma unroll
        for (int e = 0; e < NEXP; e++)
            p[e] += __shfl_xor_sync(0xffffffffu, p[e], off);
    }

    __shared__ float sm[4][NEXP];
    const int wid = threadIdx.x >> 5, lane = threadIdx.x & 31;
    if (lane == 0) {
#pragma unroll
        for (int e = 0; e < NEXP; e++) sm[wid][e] = p[e];
    }
    __syncthreads();

    if (threadIdx.x == 0) {
        float logit[NEXP];
#pragma unroll
        for (int e = 0; e < NEXP; e++)
            logit[e] = sm[0][e] + sm[1][e] + sm[2][e] + sm[3][e] + gb[e];

        float mx = logit[0];
#pragma unroll
        for (int e = 1; e < NEXP; e++) mx = fmaxf(mx, logit[e]);
        float pr[NEXP], den = 0.f;
#pragma unroll
        for (int e = 0; e < NEXP; e++) { pr[e] = __expf(logit[e] - mx); den += pr[e]; }
#pragma unroll
        for (int e = 0; e < NEXP; e++) pr[e] /= den;

        float bi[NEXP];
#pragma unroll
        for (int e = 0; e < NEXP; e++) bi[e] = pr[e] + biases[e];

        bool used[NEXP] = {false, false, false, false, false, false, false};
        int sel[TOPK];
#pragma unroll
        for (int k = 0; k < TOPK; k++) {
            int best = -1; float bv = -1e30f;
#pragma unroll
            for (int e = 0; e < NEXP; e++)
                if (!used[e] && bi[e] > bv) { bv = bi[e]; best = e; }
            used[best] = true; sel[k] = best;
        }
        float ws = pr[sel[0]] + pr[sel[1]] + pr[sel[2]];

#pragma unroll
        for (int k = 0; k < TOPK; k++) {
            int e = sel[k];
            float w = pr[e] / ws;
            int pos = atomicAdd(&g_cnt[e], 1);
            g_idx[e][pos] = t;
            g_te[t][k] = e;
            g_tp[t][k] = pos;
            g_tw[t][k] = w;
        }
    }
}

// ============================================================================
// GEMM1 (all experts, fp16): act[z] = silu(Xg @ W1[z]) * (Xg @ Wg[z])
// A: [m][k] fp16; B (transposed weights): [n][k] fp16. m16n8k16 HMMA, f32 acc.
// ============================================================================
__global__ void __launch_bounds__(NTHREADS, 1)
gemm1_all() {
    extern __shared__ __half smemh[];
    const int z = blockIdx.z;

    const __half *B1p, *Bgp;
    int cnt;
    const int* idxp;
    if (z < NEXP) {
        B1p = g_w1h + (size_t)z * D_DIM * H_DIM;
        Bgp = g_wgh + (size_t)z * D_DIM * H_DIM;
        cnt = g_cnt[z];
        idxp = g_idx[z];
    } else {
        B1p = g_ws1h; Bgp = g_wsgh; cnt = T_TOK; idxp = nullptr;
    }

    const int m0 = blockIdx.x * BM;
    if (m0 >= cnt) return;
    const int n0 = blockIdx.y * BN;
    const int tid = threadIdx.x;

    int trow[4];
#pragma unroll
    for (int i = 0; i < 4; i++) {
        int r = m0 + ((tid + i * NTHREADS) >> 3);
        int t;
        if (idxp) t = (r < cnt) ? idxp[r] : 0;
        else      t = r;
        trow[i] = t;
    }

    auto load_stage = [&](int s, int k0) {
        __half* xb = smemh + s * ST1H;
        __half* b1 = xb + TILEH;
        __half* bg = b1 + TILEH;
#pragma unroll
        for (int i = 0; i < 4; i++) {
            int c = tid + i * NTHREADS;
            int r = c >> 3, j = c & 7;
            cpa16((uint32_t)__cvta_generic_to_shared(xb + r * XSTRH + j * 8),
                  g_xh + (size_t)trow[i] * D_DIM + k0 + j * 8);
        }
#pragma unroll
        for (int i = 0; i < 4; i++) {
            int c = tid + i * NTHREADS;
            int r = c >> 3, j = c & 7;
            cpa16((uint32_t)__cvta_generic_to_shared(b1 + r * XSTRH + j * 8),
                  B1p + (size_t)(n0 + r) * D_DIM + k0 + j * 8);
            cpa16((uint32_t)__cvta_generic_to_shared(bg + r * XSTRH + j * 8),
                  Bgp + (size_t)(n0 + r) * D_DIM + k0 + j * 8);
        }
        cpa_commit();
    };

    float acc1[4][4][4];
    float accg[4][4][4];
#pragma unroll
    for (int i = 0; i < 4; i++)
#pragma unroll
        for (int j = 0; j < 4; j++)
#pragma unroll
            for (int r = 0; r < 4; r++) { acc1[i][j][r] = 0.f; accg[i][j][r] = 0.f; }

    const int wid = tid >> 5, lane = tid & 31;
    const int wm = (wid & 1) * 64, wn = (wid >> 1) * 32;
    const int qr = lane >> 2, qk = lane & 3;

    load_stage(0, 0);
    for (int it = 0; it < NIT; ++it) {
        if (it + 1 < NIT) { load_stage((it + 1) & 1, (it + 1) * BKH); cpa_wait1(); }
        else              { cpa_wait0(); }
        __syncthreads();

        const uint32_t* xw  = (const uint32_t*)(smemh + (it & 1) * ST1H);
        const uint32_t* b1w = xw + TILEH / 2;
        const uint32_t* bgw = b1w + TILEH / 2;

#pragma unroll
        for (int kk = 0; kk < 4; kk++) {      // 4 x K=16 steps per 64-half chunk
            const int kw = kk * 8;
            uint32_t a[4][4];
#pragma unroll
            for (int mf = 0; mf < 4; mf++) {
                int base = (wm + mf * 16 + qr) * XSTRW + kw + qk;
                a[mf][0] = xw[base];
                a[mf][1] = xw[base + 8 * XSTRW];
                a[mf][2] = xw[base + 4];
                a[mf][3] = xw[base + 8 * XSTRW + 4];
            }
#pragma unroll
            for (int nf = 0; nf < 4; nf++) {
                int nb = (wn + nf * 8 + qr) * XSTRW + kw + qk;
                uint32_t f10 = b1w[nb], f11 = b1w[nb + 4];
                uint32_t fg0 = bgw[nb], fg1 = bgw[nb + 4];
#pragma unroll
                for (int mf = 0; mf < 4; mf++) {
                    mma_f16(acc1[mf][nf], a[mf], f10, f11);
                    mma_f16(accg[mf][nf], a[mf], fg0, fg1);
                }
            }
        }
        __syncthreads();
    }

    // epilogue: fp16(silu(acc1)*accg) -> g_acth[z]
    __half* actp = g_acth[z];
#pragma unroll
    for (int mf = 0; mf < 4; mf++) {
        int r0 = m0 + wm + mf * 16 + qr;
        int r1 = r0 + 8;
#pragma unroll
        for (int nf = 0; nf < 4; nf++) {
            int cl = n0 + wn + nf * 8 + qk * 2;
            __half2 h0 = __floats2half2_rn(silu_f(acc1[mf][nf][0]) * accg[mf][nf][0],
                                           silu_f(acc1[mf][nf][1]) * accg[mf][nf][1]);
            __half2 h1 = __floats2half2_rn(silu_f(acc1[mf][nf][2]) * accg[mf][nf][2],
                                           silu_f(acc1[mf][nf][3]) * accg[mf][nf][3]);
            *(__half2*)(actp + (size_t)r0 * H_DIM + cl) = h0;
            *(__half2*)(actp + (size_t)r1 * H_DIM + cl) = h1;
        }
    }
}

// ============================================================================
// GEMM2 (all experts, fp16): y = act[z] @ W2[z]
// ============================================================================
__global__ void __launch_bounds__(NTHREADS, 1)
gemm2_all(float* __restrict__ out) {
    extern __shared__ __half smemh[];
    const int z = blockIdx.z;

    const __half* Bp;
    int cnt;
    if (z < NEXP) { Bp = g_w2h + (size_t)z * H_DIM * D_DIM; cnt = g_cnt[z]; }
    else          { Bp = g_ws2h; cnt = T_TOK; }
    const __half* Ap = g_acth[z];

    const int m0 = blockIdx.x * BM;
    if (m0 >= cnt) return;
    const int n0 = blockIdx.y * BN;
    const int tid = threadIdx.x;

    auto load_stage = [&](int s, int k0) {
        __half* ab = smemh + s * ST2H;
        __half* bb = ab + TILEH;
#pragma unroll
        for (int i = 0; i < 4; i++) {
            int c = tid + i * NTHREADS;
            int r = c >> 3, j = c & 7;
            cpa16((uint32_t)__cvta_generic_to_shared(ab + r * XSTRH + j * 8),
                  Ap + (size_t)(m0 + r) * H_DIM + k0 + j * 8);
        }
#pragma unroll
        for (int i = 0; i < 4; i++) {
            int c = tid + i * NTHREADS;
            int r = c >> 3, j = c & 7;
            cpa16((uint32_t)__cvta_generic_to_shared(bb + r * XSTRH + j * 8),
                  Bp + (size_t)(n0 + r) * H_DIM + k0 + j * 8);
        }
        cpa_commit();
    };

    float acc[4][4][4];
#pragma unroll
    for (int i = 0; i < 4; i++)
#pragma unroll
        for (int j = 0; j < 4; j++)
#pragma unroll
            for (int r = 0; r < 4; r++) acc[i][j][r] = 0.f;

    const int wid = tid >> 5, lane = tid & 31;
    const int wm = (wid & 1) * 64, wn = (wid >> 1) * 32;
    const int qr = lane >> 2, qk = lane & 3;

    load_stage(0, 0);
    for (int it = 0; it < NIT; ++it) {
        if (it + 1 < NIT) { load_stage((it + 1) & 1, (it + 1) * BKH); cpa_wait1(); }
        else              { cpa_wait0(); }
        __syncthreads();

        const uint32_t* aw = (const uint32_t*)(smemh + (it & 1) * ST2H);
        const uint32_t* bw = aw + TILEH / 2;

#pragma unroll
        for (int kk = 0; kk < 4; kk++) {
            const int kw = kk * 8;
            uint32_t a[4][4];
#pragma unroll
            for (int mf = 0; mf < 4; mf++) {
                int base = (wm + mf * 16 + qr) * XSTRW + kw + qk;
                a[mf][0] = aw[base];
                a[mf][1] = aw[base + 8 * XSTRW];
                a[mf][2] = aw[base + 4];
                a[mf][3] = aw[base + 8 * XSTRW + 4];
            }
#pragma unroll
            for (int nf = 0; nf < 4; nf++) {
                int nb = (wn + nf * 8 + qr) * XSTRW + kw + qk;
                uint32_t b0 = bw[nb], b1 = bw[nb + 4];
#pragma unroll
                for (int mf = 0; mf < 4; mf++) mma_f16(acc[mf][nf], a[mf], b0, b1);
            }
        }
        __syncthreads();
    }

#pragma unroll
    for (int mf = 0; mf < 4; mf++) {
        int r0 = m0 + wm + mf * 16 + qr;
        int r1 = r0 + 8;
#pragma unroll
        for (int nf = 0; nf < 4; nf++) {
            int cl = n0 + wn + nf * 8 + qk * 2;
            float2 v0 = { acc[mf][nf][0], acc[mf][nf][1] };
            float2 v1 = { acc[mf][nf][2], acc[mf][nf][3] };
            if (z == NEXP) {
                *(float2*)(out + (size_t)r0 * D_DIM + cl) = v0;
                *(float2*)(out + (size_t)r1 * D_DIM + cl) = v1;
            } else {
                float* yp = g_y[z];
                if (r0 < cnt) *(float2*)(yp + (size_t)r0 * D_DIM + cl) = v0;
                if (r1 < cnt) *(float2*)(yp + (size_t)r1 * D_DIM + cl) = v1;
            }
        }
    }
}

// ============================================================================
// combine: out[t] += sum_k w_k * y[e_k][pos_k]
// ============================================================================
__global__ void combine_kernel(float* __restrict__ out) {
    const int t = blockIdx.x;
    const int e0 = g_te[t][0], e1 = g_te[t][1], e2 = g_te[t][2];
    const float w0 = g_tw[t][0], w1 = g_tw[t][1], w2 = g_tw[t][2];
    const float4* y0 = (const float4*)(g_y[e0] + (size_t)g_tp[t][0] * D_DIM);
    const float4* y1 = (const float4*)(g_y[e1] + (size_t)g_tp[t][1] * D_DIM);
    const float4* y2 = (const float4*)(g_y[e2] + (size_t)g_tp[t][2] * D_DIM);
    float4* o = (float4*)(out + (size_t)t * D_DIM);

    for (int i = threadIdx.x; i < D_DIM / 4; i += 256) {
        float4 v = o[i];
        float4 a = y0[i], b = y1[i], c = y2[i];
        v.x += w0 * a.x + w1 * b.x + w2 * c.x;
        v.y += w0 * a.y + w1 * b.y + w2 * c.y;
        v.z += w0 * a.z + w1 * b.z + w2 * c.z;
        v.w += w0 * a.w + w1 * b.w + w2 * c.w;
        o[i] = v;
    }
}

// ============================================================================
// launcher
// ============================================================================
extern "C" void kernel_launch(void* const* d_in, const int* in_sizes, int n_in,
                              void* d_out, int out_size) {
    const float* x    = (const float*)d_in[0];
    const float* W1   = (const float*)d_in[1];
    const float* Wg   = (const float*)d_in[2];
    const float* W2   = (const float*)d_in[3];
    const float* Ws1  = (const float*)d_in[4];
    const float* Wsg  = (const float*)d_in[5];
    const float* Ws2  = (const float*)d_in[6];
    const float* gw   = (const float*)d_in[7];
    const float* gb   = (const float*)d_in[8];
    const float* bias = (const float*)d_in[9];
    float* out = (float*)d_out;
    (void)in_sizes; (void)n_in; (void)out_size;

    cudaFuncSetAttribute(gemm1_all, cudaFuncAttributeMaxDynamicSharedMemorySize, SMEM1_BYTES);
    cudaFuncSetAttribute(gemm2_all, cudaFuncAttributeMaxDynamicSharedMemorySize, SMEM2_BYTES);

    __half *w1h, *wgh, *w2h, *ws1h, *wsgh, *ws2h, *xh;
    cudaGetSymbolAddress((void**)&w1h,  g_w1h);
    cudaGetSymbolAddress((void**)&wgh,  g_wgh);
    cudaGetSymbolAddress((void**)&w2h,  g_w2h);
    cudaGetSymbolAddress((void**)&ws1h, g_ws1h);
    cudaGetSymbolAddress((void**)&wsgh, g_wsgh);
    cudaGetSymbolAddress((void**)&ws2h, g_ws2h);
    cudaGetSymbolAddress((void**)&xh,   g_xh);

    dim3 tb(32, 8);
    cvtT_kernel<<<dim3(32, 64, NEXP), tb>>>(W1,  w1h);
    cvtT_kernel<<<dim3(32, 64, NEXP), tb>>>(Wg,  wgh);
    cvtT_kernel<<<dim3(32, 64, NEXP), tb>>>(W2,  w2h);
    cvtT_kernel<<<dim3(32, 64, 1),    tb>>>(Ws1, ws1h);
    cvtT_kernel<<<dim3(32, 64, 1),    tb>>>(Wsg, wsgh);
    cvtT_kernel<<<dim3(32, 64, 1),    tb>>>(Ws2, ws2h);
    cvtX_kernel<<<2048, 256>>>(x, xh, (int)(XELEMS / 2));

    zero_cnt<<<1, 32>>>();
    gate_kernel<<<T_TOK, 128>>>(x, gw, gb, bias);
    gemm1_all<<<dim3(T_TOK / BM, H_DIM / BN, 8), NTHREADS, SMEM1_BYTES>>>();
    gemm2_all<<<dim3(T_TOK / BM, D_DIM / BN, 8), NTHREADS, SMEM2_BYTES>>>(out);
    combine_kernel<<<T_TOK, 256>>>(out);
}

// round 6
// speedup vs baseline: 9.4206x; 1.0196x over previous
#include <cuda_runtime.h>
#include <cuda_fp16.h>
#include <cstdint>

// ---------------- problem constants ----------------
#define T_TOK 8192
#define D_DIM 2048
#define H_DIM 2048
#define NEXP  7
#define TOPK  3

// ---------------- tiling ----------------
#define BM 128
#define BN 128
#define BKH 64                 // K-chunk in halfs (128B per row)
#define NTHREADS 256
#define XSTRH 72               // halfs per smem row (padded; conflict-free)
#define NIT (D_DIM / BKH)      // 32 k-iterations

#define TILE_B (128 * XSTRH * 2)       // bytes per 128-row tile = 18432
#define STAGE1B (3 * TILE_B)           // gemm1 stage bytes (A + B1 + Bg) = 55296
#define STAGE2B (2 * TILE_B)           // gemm2 stage bytes (A + B) = 36864
#define NS1 3
#define NS2 4
#define SMEM1_BYTES (NS1 * STAGE1B)    // 165888
#define SMEM2_BYTES (NS2 * STAGE2B)    // 147456

#define WELEMS ((size_t)NEXP * D_DIM * H_DIM)
#define SELEMS ((size_t)D_DIM * H_DIM)
#define XELEMS ((size_t)T_TOK * D_DIM)

// ---------------- device scratch (no allocations allowed) ----------------
__device__ int   g_cnt[NEXP];
__device__ __align__(16) int   g_idx[NEXP][T_TOK];
__device__ int   g_te[T_TOK][TOPK];
__device__ int   g_tp[T_TOK][TOPK];
__device__ float g_tw[T_TOK][TOPK];

__device__ __align__(16) __half g_acth[8][(size_t)T_TOK * H_DIM];   // fp16 SwiGLU acts
__device__ __align__(16) float  g_y[NEXP][(size_t)T_TOK * D_DIM];   // staged routed outputs

// fp16 operands: weights TRANSPOSED to [n][k]; x row-major [m][k]
__device__ __align__(16) __half g_w1h[WELEMS];
__device__ __align__(16) __half g_wgh[WELEMS];
__device__ __align__(16) __half g_w2h[WELEMS];
__device__ __align__(16) __half g_ws1h[SELEMS];
__device__ __align__(16) __half g_wsgh[SELEMS];
__device__ __align__(16) __half g_ws2h[SELEMS];
__device__ __align__(16) __half g_xh[XELEMS];

// ---------------- helpers ----------------
__device__ __forceinline__ float silu_f(float z) {
    return z / (1.0f + __expf(-z));
}

__device__ __forceinline__ void mma_f16(float c[4], const uint32_t a[4],
                                        const uint32_t b0, const uint32_t b1) {
    asm volatile(
        "mma.sync.aligned.m16n8k16.row.col.f32.f16.f16.f32 "
        "{%0,%1,%2,%3}, {%4,%5,%6,%7}, {%8,%9}, {%0,%1,%2,%3};\n"
        : "+f"(c[0]), "+f"(c[1]), "+f"(c[2]), "+f"(c[3])
        : "r"(a[0]), "r"(a[1]), "r"(a[2]), "r"(a[3]),
          "r"(b0), "r"(b1));
}

#define LDSM4(r, addr) \
    asm volatile("ldmatrix.sync.aligned.m8n8.x4.shared.b16 {%0,%1,%2,%3}, [%4];" \
                 : "=r"((r)[0]), "=r"((r)[1]), "=r"((r)[2]), "=r"((r)[3]) \
                 : "r"(addr))

__device__ __forceinline__ void cpa16(uint32_t saddr, const void* gptr) {
    asm volatile("cp.async.cg.shared.global [%0], [%1], 16;\n" :: "r"(saddr), "l"(gptr));
}
__device__ __forceinline__ void cpa_commit() {
    asm volatile("cp.async.commit_group;\n" ::: "memory");
}
__device__ __forceinline__ void cpa_wait1() {
    asm volatile("cp.async.wait_group 1;\n" ::: "memory");
}
__device__ __forceinline__ void cpa_wait2() {
    asm volatile("cp.async.wait_group 2;\n" ::: "memory");
}

// ============================================================================
// weight convert + transpose: src f32 [K=2048][N=2048] -> dst fp16 [N][K]
// ============================================================================
__global__ void cvtT_kernel(const float* __restrict__ src, __half* __restrict__ dst) {
    __shared__ float sm[64][33];
    const size_t moff = (size_t)blockIdx.z * 2048 * 2048;
    const int k0 = blockIdx.x * 64;
    const int n0 = blockIdx.y * 32;
    const int tx = threadIdx.x, ty = threadIdx.y;

#pragma unroll
    for (int i = 0; i < 8; i++) {
        int ky = ty + i * 8;
        sm[ky][tx] = src[moff + (size_t)(k0 + ky) * 2048 + n0 + tx];
    }
    __syncthreads();

#pragma unroll
    for (int j = 0; j < 4; j++) {
        int ny = ty + j * 8;
        __half* drow = dst + moff + (size_t)(n0 + ny) * 2048 + k0;
        drow[tx]      = __float2half(sm[tx][ny]);
        drow[tx + 32] = __float2half(sm[tx + 32][ny]);
    }
}

// ============================================================================
// x convert: f32 -> fp16
// ============================================================================
__global__ void cvtX_kernel(const float* __restrict__ src, __half* __restrict__ dst,
                            int n2) {
    for (int i = blockIdx.x * blockDim.x + threadIdx.x; i < n2;
         i += gridDim.x * blockDim.x) {
        float2 v = ((const float2*)src)[i];
        ((__half2*)dst)[i] = __floats2half2_rn(v.x, v.y);
    }
}

// ============================================================================
// zero routing counters
// ============================================================================
__global__ void zero_cnt() {
    if (threadIdx.x < NEXP) g_cnt[threadIdx.x] = 0;
}

// ============================================================================
// gate (fp32)
// ============================================================================
__global__ void gate_kernel(const float* __restrict__ x,
                            const float* __restrict__ gw,
                            const float* __restrict__ gb,
                            const float* __restrict__ biases) {
    const int t = blockIdx.x;
    const float* xr = x + (size_t)t * D_DIM;

    float p[NEXP];
#pragma unroll
    for (int e = 0; e < NEXP; e++) p[e] = 0.f;

    for (int i = threadIdx.x; i < D_DIM; i += 128) {
        float xv = xr[i];
        const float* g = gw + (size_t)i * NEXP;
#pragma unroll
        for (int e = 0; e < NEXP; e++) p[e] += xv * g[e];
    }
#pragma unroll
    for (int off = 16; off > 0; off >>= 1) {
#pragma unroll
        for (int e = 0; e < NEXP; e++)
            p[e] += __shfl_xor_sync(0xffffffffu, p[e], off);
    }

    __shared__ float sm[4][NEXP];
    const int wid = threadIdx.x >> 5, lane = threadIdx.x & 31;
    if (lane == 0) {
#pragma unroll
        for (int e = 0; e < NEXP; e++) sm[wid][e] = p[e];
    }
    __syncthreads();

    if (threadIdx.x == 0) {
        float logit[NEXP];
#pragma unroll
        for (int e = 0; e < NEXP; e++)
            logit[e] = sm[0][e] + sm[1][e] + sm[2][e] + sm[3][e] + gb[e];

        float mx = logit[0];
#pragma unroll
        for (int e = 1; e < NEXP; e++) mx = fmaxf(mx, logit[e]);
        float pr[NEXP], den = 0.f;
#pragma unroll
        for (int e = 0; e < NEXP; e++) { pr[e] = __expf(logit[e] - mx); den += pr[e]; }
#pragma unroll
        for (int e = 0; e < NEXP; e++) pr[e] /= den;

        float bi[NEXP];
#pragma unroll
        for (int e = 0; e < NEXP; e++) bi[e] = pr[e] + biases[e];

        bool used[NEXP] = {false, false, false, false, false, false, false};
        int sel[TOPK];
#pragma unroll
        for (int k = 0; k < TOPK; k++) {
            int best = -1; float bv = -1e30f;
#pragma unroll
            for (int e = 0; e < NEXP; e++)
                if (!used[e] && bi[e] > bv) { bv = bi[e]; best = e; }
            used[best] = true; sel[k] = best;
        }
        float ws = pr[sel[0]] + pr[sel[1]] + pr[sel[2]];

#pragma unroll
        for (int k = 0; k < TOPK; k++) {
            int e = sel[k];
            float w = pr[e] / ws;
            int pos = atomicAdd(&g_cnt[e], 1);
            g_idx[e][pos] = t;
            g_te[t][k] = e;
            g_tp[t][k] = pos;
            g_tw[t][k] = w;
        }
    }
}

// ============================================================================
// GEMM1 (all experts, fp16): act[z] = silu(Xg @ W1[z]) * (Xg @ Wg[z])
// 3-stage cp.async pipeline, single sync/iter, ldmatrix fragment loads.
// ============================================================================
__global__ void __launch_bounds__(NTHREADS, 1)
gemm1_all() {
    extern __shared__ __half smemh[];
    const uint32_t sbase = (uint32_t)__cvta_generic_to_shared(smemh);
    const int z = blockIdx.z;

    const __half *B1p, *Bgp;
    int cnt;
    const int* idxp;
    if (z < NEXP) {
        B1p = g_w1h + (size_t)z * D_DIM * H_DIM;
        Bgp = g_wgh + (size_t)z * D_DIM * H_DIM;
        cnt = g_cnt[z];
        idxp = g_idx[z];
    } else {
        B1p = g_ws1h; Bgp = g_wsgh; cnt = T_TOK; idxp = nullptr;
    }

    const int m0 = blockIdx.x * BM;
    if (m0 >= cnt) return;
    const int n0 = blockIdx.y * BN;
    const int tid = threadIdx.x;

    int trow[4];
#pragma unroll
    for (int i = 0; i < 4; i++) {
        int r = m0 + ((tid + i * NTHREADS) >> 3);
        int t;
        if (idxp) t = (r < cnt) ? idxp[r] : 0;
        else      t = r;
        trow[i] = t;
    }

    auto load_stage = [&](int s, int k0) {
        const uint32_t xb = sbase + s * STAGE1B;
        const uint32_t b1 = xb + TILE_B;
        const uint32_t bg = b1 + TILE_B;
#pragma unroll
        for (int i = 0; i < 4; i++) {
            int c = tid + i * NTHREADS;
            int r = c >> 3, j = c & 7;
            cpa16(xb + (r * XSTRH + j * 8) * 2,
                  g_xh + (size_t)trow[i] * D_DIM + k0 + j * 8);
        }
#pragma unroll
        for (int i = 0; i < 4; i++) {
            int c = tid + i * NTHREADS;
            int r = c >> 3, j = c & 7;
            cpa16(b1 + (r * XSTRH + j * 8) * 2,
                  B1p + (size_t)(n0 + r) * D_DIM + k0 + j * 8);
            cpa16(bg + (r * XSTRH + j * 8) * 2,
                  Bgp + (size_t)(n0 + r) * D_DIM + k0 + j * 8);
        }
        cpa_commit();
    };

    float acc1[4][4][4];
    float accg[4][4][4];
#pragma unroll
    for (int i = 0; i < 4; i++)
#pragma unroll
        for (int j = 0; j < 4; j++)
#pragma unroll
            for (int r = 0; r < 4; r++) { acc1[i][j][r] = 0.f; accg[i][j][r] = 0.f; }

    const int wid = tid >> 5, lane = tid & 31;
    const int wm = (wid & 1) * 64, wn = (wid >> 1) * 32;
    const int qr = lane >> 2, qk = lane & 3;

    // ldmatrix lane address offsets (bytes from tile base)
    const int l8 = lane & 7;
    uint32_t a_off[4], b_off[2];
#pragma unroll
    for (int mf = 0; mf < 4; mf++)
        a_off[mf] = ((wm + mf * 16 + l8 + ((lane >> 3) & 1) * 8) * XSTRH
                     + ((lane >> 4) & 1) * 8) * 2;
#pragma unroll
    for (int p = 0; p < 2; p++)
        b_off[p] = ((wn + p * 16 + l8 + ((lane >> 4) & 1) * 8) * XSTRH
                    + ((lane >> 3) & 1) * 8) * 2;

    load_stage(0, 0);
    load_stage(1, BKH);
    for (int it = 0; it < NIT; ++it) {
        cpa_wait1();
        __syncthreads();
        if (it + NS1 - 1 < NIT) load_stage((it + NS1 - 1) % NS1, (it + NS1 - 1) * BKH);

        const uint32_t xb = sbase + (it % NS1) * STAGE1B;
        const uint32_t b1 = xb + TILE_B;
        const uint32_t bg = b1 + TILE_B;

#pragma unroll
        for (int kk = 0; kk < 4; kk++) {
            const int kb = kk * 32;       // 16 halfs per K-step
            uint32_t a[4][4];
#pragma unroll
            for (int mf = 0; mf < 4; mf++) LDSM4(a[mf], xb + a_off[mf] + kb);
#pragma unroll
            for (int p = 0; p < 2; p++) {
                uint32_t b[4], g[4];
                LDSM4(b, b1 + b_off[p] + kb);
                LDSM4(g, bg + b_off[p] + kb);
#pragma unroll
                for (int mf = 0; mf < 4; mf++) {
                    mma_f16(acc1[mf][2 * p],     a[mf], b[0], b[1]);
                    mma_f16(acc1[mf][2 * p + 1], a[mf], b[2], b[3]);
                    mma_f16(accg[mf][2 * p],     a[mf], g[0], g[1]);
                    mma_f16(accg[mf][2 * p + 1], a[mf], g[2], g[3]);
                }
            }
        }
    }

    // epilogue: fp16(silu(acc1)*accg) -> g_acth[z]
    __half* actp = g_acth[z];
#pragma unroll
    for (int mf = 0; mf < 4; mf++) {
        int r0 = m0 + wm + mf * 16 + qr;
        int r1 = r0 + 8;
#pragma unroll
        for (int nf = 0; nf < 4; nf++) {
            int cl = n0 + wn + nf * 8 + qk * 2;
            __half2 h0 = __floats2half2_rn(silu_f(acc1[mf][nf][0]) * accg[mf][nf][0],
                                           silu_f(acc1[mf][nf][1]) * accg[mf][nf][1]);
            __half2 h1 = __floats2half2_rn(silu_f(acc1[mf][nf][2]) * accg[mf][nf][2],
                                           silu_f(acc1[mf][nf][3]) * accg[mf][nf][3]);
            *(__half2*)(actp + (size_t)r0 * H_DIM + cl) = h0;
            *(__half2*)(actp + (size_t)r1 * H_DIM + cl) = h1;
        }
    }
}

// ============================================================================
// GEMM2 (all experts, fp16): y = act[z] @ W2[z]
// 4-stage cp.async pipeline, single sync/iter, ldmatrix fragment loads.
// ============================================================================
__global__ void __launch_bounds__(NTHREADS, 1)
gemm2_all(float* __restrict__ out) {
    extern __shared__ __half smemh[];
    const uint32_t sbase = (uint32_t)__cvta_generic_to_shared(smemh);
    const int z = blockIdx.z;

    const __half* Bp;
    int cnt;
    if (z < NEXP) { Bp = g_w2h + (size_t)z * H_DIM * D_DIM; cnt = g_cnt[z]; }
    else          { Bp = g_ws2h; cnt = T_TOK; }
    const __half* Ap = g_acth[z];

    const int m0 = blockIdx.x * BM;
    if (m0 >= cnt) return;
    const int n0 = blockIdx.y * BN;
    const int tid = threadIdx.x;

    auto load_stage = [&](int s, int k0) {
        const uint32_t ab = sbase + s * STAGE2B;
        const uint32_t bb = ab + TILE_B;
#pragma unroll
        for (int i = 0; i < 4; i++) {
            int c = tid + i * NTHREADS;
            int r = c >> 3, j = c & 7;
            cpa16(ab + (r * XSTRH + j * 8) * 2,
                  Ap + (size_t)(m0 + r) * H_DIM + k0 + j * 8);
        }
#pragma unroll
        for (int i = 0; i < 4; i++) {
            int c = tid + i * NTHREADS;
            int r = c >> 3, j = c & 7;
            cpa16(bb + (r * XSTRH + j * 8) * 2,
                  Bp + (size_t)(n0 + r) * H_DIM + k0 + j * 8);
        }
        cpa_commit();
    };

    float acc[4][4][4];
#pragma unroll
    for (int i = 0; i < 4; i++)
#pragma unroll
        for (int j = 0; j < 4; j++)
#pragma unroll
            for (int r = 0; r < 4; r++) acc[i][j][r] = 0.f;

    const int wid = tid >> 5, lane = tid & 31;
    const int wm = (wid & 1) * 64, wn = (wid >> 1) * 32;
    const int qr = lane >> 2, qk = lane & 3;

    const int l8 = lane & 7;
    uint32_t a_off[4], b_off[2];
#pragma unroll
    for (int mf = 0; mf < 4; mf++)
        a_off[mf] = ((wm + mf * 16 + l8 + ((lane >> 3) & 1) * 8) * XSTRH
                     + ((lane >> 4) & 1) * 8) * 2;
#pragma unroll
    for (int p = 0; p < 2; p++)
        b_off[p] = ((wn + p * 16 + l8 + ((lane >> 4) & 1) * 8) * XSTRH
                    + ((lane >> 3) & 1) * 8) * 2;

    load_stage(0, 0);
    load_stage(1, BKH);
    load_stage(2, 2 * BKH);
    for (int it = 0; it < NIT; ++it) {
        cpa_wait2();
        __syncthreads();
        if (it + NS2 - 1 < NIT) load_stage((it + NS2 - 1) % NS2, (it + NS2 - 1) * BKH);

        const uint32_t ab = sbase + (it % NS2) * STAGE2B;
        const uint32_t bb = ab + TILE_B;

#pragma unroll
        for (int kk = 0; kk < 4; kk++) {
            const int kb = kk * 32;
            uint32_t a[4][4];
#pragma unroll
            for (int mf = 0; mf < 4; mf++) LDSM4(a[mf], ab + a_off[mf] + kb);
#pragma unroll
            for (int p = 0; p < 2; p++) {
                uint32_t b[4];
                LDSM4(b, bb + b_off[p] + kb);
#pragma unroll
                for (int mf = 0; mf < 4; mf++) {
                    mma_f16(acc[mf][2 * p],     a[mf], b[0], b[1]);
                    mma_f16(acc[mf][2 * p + 1], a[mf], b[2], b[3]);
                }
            }
        }
    }

#pragma unroll
    for (int mf = 0; mf < 4; mf++) {
        int r0 = m0 + wm + mf * 16 + qr;
        int r1 = r0 + 8;
#pragma unroll
        for (int nf = 0; nf < 4; nf++) {
            int cl = n0 + wn + nf * 8 + qk * 2;
            float2 v0 = { acc[mf][nf][0], acc[mf][nf][1] };
            float2 v1 = { acc[mf][nf][2], acc[mf][nf][3] };
            if (z == NEXP) {
                *(float2*)(out + (size_t)r0 * D_DIM + cl) = v0;
                *(float2*)(out + (size_t)r1 * D_DIM + cl) = v1;
            } else {
                float* yp = g_y[z];
                if (r0 < cnt) *(float2*)(yp + (size_t)r0 * D_DIM + cl) = v0;
                if (r1 < cnt) *(float2*)(yp + (size_t)r1 * D_DIM + cl) = v1;
            }
        }
    }
}

// ============================================================================
// combine: out[t] += sum_k w_k * y[e_k][pos_k]
// ============================================================================
__global__ void combine_kernel(float* __restrict__ out) {
    const int t = blockIdx.x;
    const int e0 = g_te[t][0], e1 = g_te[t][1], e2 = g_te[t][2];
    const float w0 = g_tw[t][0], w1 = g_tw[t][1], w2 = g_tw[t][2];
    const float4* y0 = (const float4*)(g_y[e0] + (size_t)g_tp[t][0] * D_DIM);
    const float4* y1 = (const float4*)(g_y[e1] + (size_t)g_tp[t][1] * D_DIM);
    const float4* y2 = (const float4*)(g_y[e2] + (size_t)g_tp[t][2] * D_DIM);
    float4* o = (float4*)(out + (size_t)t * D_DIM);

    for (int i = threadIdx.x; i < D_DIM / 4; i += 256) {
        float4 v = o[i];
        float4 a = y0[i], b = y1[i], c = y2[i];
        v.x += w0 * a.x + w1 * b.x + w2 * c.x;
        v.y += w0 * a.y + w1 * b.y + w2 * c.y;
        v.z += w0 * a.z + w1 * b.z + w2 * c.z;
        v.w += w0 * a.w + w1 * b.w + w2 * c.w;
        o[i] = v;
    }
}

// ============================================================================
// launcher
// ============================================================================
extern "C" void kernel_launch(void* const* d_in, const int* in_sizes, int n_in,
                              void* d_out, int out_size) {
    const float* x    = (const float*)d_in[0];
    const float* W1   = (const float*)d_in[1];
    const float* Wg   = (const float*)d_in[2];
    const float* W2   = (const float*)d_in[3];
    const float* Ws1  = (const float*)d_in[4];
    const float* Wsg  = (const float*)d_in[5];
    const float* Ws2  = (const float*)d_in[6];
    const float* gw   = (const float*)d_in[7];
    const float* gb   = (const float*)d_in[8];
    const float* bias = (const float*)d_in[9];
    float* out = (float*)d_out;
    (void)in_sizes; (void)n_in; (void)out_size;

    cudaFuncSetAttribute(gemm1_all, cudaFuncAttributeMaxDynamicSharedMemorySize, SMEM1_BYTES);
    cudaFuncSetAttribute(gemm2_all, cudaFuncAttributeMaxDynamicSharedMemorySize, SMEM2_BYTES);

    __half *w1h, *wgh, *w2h, *ws1h, *wsgh, *ws2h, *xh;
    cudaGetSymbolAddress((void**)&w1h,  g_w1h);
    cudaGetSymbolAddress((void**)&wgh,  g_wgh);
    cudaGetSymbolAddress((void**)&w2h,  g_w2h);
    cudaGetSymbolAddress((void**)&ws1h, g_ws1h);
    cudaGetSymbolAddress((void**)&wsgh, g_wsgh);
    cudaGetSymbolAddress((void**)&ws2h, g_ws2h);
    cudaGetSymbolAddress((void**)&xh,   g_xh);

    dim3 tb(32, 8);
    cvtT_kernel<<<dim3(32, 64, NEXP), tb>>>(W1,  w1h);
    cvtT_kernel<<<dim3(32, 64, NEXP), tb>>>(Wg,  wgh);
    cvtT_kernel<<<dim3(32, 64, NEXP), tb>>>(W2,  w2h);
    cvtT_kernel<<<dim3(32, 64, 1),    tb>>>(Ws1, ws1h);
    cvtT_kernel<<<dim3(32, 64, 1),    tb>>>(Wsg, wsgh);
    cvtT_kernel<<<dim3(32, 64, 1),    tb>>>(Ws2, ws2h);
    cvtX_kernel<<<2048, 256>>>(x, xh, (int)(XELEMS / 2));

    zero_cnt<<<1, 32>>>();
    gate_kernel<<<T_TOK, 128>>>(x, gw, gb, bias);
    gemm1_all<<<dim3(T_TOK / BM, H_DIM / BN, 8), NTHREADS, SMEM1_BYTES>>>();
    gemm2_all<<<dim3(T_TOK / BM, D_DIM / BN, 8), NTHREADS, SMEM2_BYTES>>>(out);
    combine_kernel<<<T_TOK, 256>>>(out);
}

// round 7
// speedup vs baseline: 9.9300x; 1.0541x over previous
#include <cuda_runtime.h>
#include <cuda_fp16.h>
#include <cstdint>

// ---------------- problem constants ----------------
#define T_TOK 8192
#define D_DIM 2048
#define H_DIM 2048
#define NEXP  7
#define TOPK  3

// ---------------- tiling ----------------
#define BM 128
#define BN 128
#define BKH 64                 // K-chunk in halfs (128B per row)
#define NTHREADS 512           // 16 warps, warp grid 4m x 4n, warp tile 32x32
#define XSTRH 72               // halfs per smem row (padded; conflict-free)
#define NIT (D_DIM / BKH)      // 32 k-iterations

#define TILE_B (128 * XSTRH * 2)       // bytes per 128-row tile = 18432
#define STAGE1B (3 * TILE_B)           // gemm1 stage bytes (A + B1 + Bg) = 55296
#define STAGE2B (2 * TILE_B)           // gemm2 stage bytes (A + B) = 36864
#define NS1 3
#define NS2 4
#define SMEM1_BYTES (NS1 * STAGE1B)    // 165888
#define SMEM2_BYTES (NS2 * STAGE2B)    // 147456

#define WELEMS ((size_t)NEXP * D_DIM * H_DIM)
#define SELEMS ((size_t)D_DIM * H_DIM)
#define XELEMS ((size_t)T_TOK * D_DIM)

// ---------------- device scratch (no allocations allowed) ----------------
__device__ int   g_cnt[NEXP];
__device__ __align__(16) int   g_idx[NEXP][T_TOK];
__device__ int   g_te[T_TOK][TOPK];
__device__ int   g_tp[T_TOK][TOPK];
__device__ float g_tw[T_TOK][TOPK];

__device__ __align__(16) __half g_acth[8][(size_t)T_TOK * H_DIM];   // fp16 SwiGLU acts
__device__ __align__(16) float  g_y[NEXP][(size_t)T_TOK * D_DIM];   // staged routed outputs

// fp16 operands: weights TRANSPOSED to [n][k]; x row-major [m][k]
__device__ __align__(16) __half g_w1h[WELEMS];
__device__ __align__(16) __half g_wgh[WELEMS];
__device__ __align__(16) __half g_w2h[WELEMS];
__device__ __align__(16) __half g_ws1h[SELEMS];
__device__ __align__(16) __half g_wsgh[SELEMS];
__device__ __align__(16) __half g_ws2h[SELEMS];
__device__ __align__(16) __half g_xh[XELEMS];

// ---------------- helpers ----------------
__device__ __forceinline__ float silu_f(float z) {
    return z / (1.0f + __expf(-z));
}

__device__ __forceinline__ void mma_f16(float c[4], const uint32_t a[4],
                                        const uint32_t b0, const uint32_t b1) {
    asm volatile(
        "mma.sync.aligned.m16n8k16.row.col.f32.f16.f16.f32 "
        "{%0,%1,%2,%3}, {%4,%5,%6,%7}, {%8,%9}, {%0,%1,%2,%3};\n"
        : "+f"(c[0]), "+f"(c[1]), "+f"(c[2]), "+f"(c[3])
        : "r"(a[0]), "r"(a[1]), "r"(a[2]), "r"(a[3]),
          "r"(b0), "r"(b1));
}

#define LDSM4(r, addr) \
    asm volatile("ldmatrix.sync.aligned.m8n8.x4.shared.b16 {%0,%1,%2,%3}, [%4];" \
                 : "=r"((r)[0]), "=r"((r)[1]), "=r"((r)[2]), "=r"((r)[3]) \
                 : "r"(addr))

__device__ __forceinline__ void cpa16(uint32_t saddr, const void* gptr) {
    asm volatile("cp.async.cg.shared.global [%0], [%1], 16;\n" :: "r"(saddr), "l"(gptr));
}
__device__ __forceinline__ void cpa_commit() {
    asm volatile("cp.async.commit_group;\n" ::: "memory");
}
__device__ __forceinline__ void cpa_wait1() {
    asm volatile("cp.async.wait_group 1;\n" ::: "memory");
}
__device__ __forceinline__ void cpa_wait2() {
    asm volatile("cp.async.wait_group 2;\n" ::: "memory");
}

// ============================================================================
// weight convert + transpose: src f32 [K=2048][N=2048] -> dst fp16 [N][K]
// ============================================================================
__global__ void cvtT_kernel(const float* __restrict__ src, __half* __restrict__ dst) {
    __shared__ float sm[64][33];
    const size_t moff = (size_t)blockIdx.z * 2048 * 2048;
    const int k0 = blockIdx.x * 64;
    const int n0 = blockIdx.y * 32;
    const int tx = threadIdx.x, ty = threadIdx.y;

#pragma unroll
    for (int i = 0; i < 8; i++) {
        int ky = ty + i * 8;
        sm[ky][tx] = src[moff + (size_t)(k0 + ky) * 2048 + n0 + tx];
    }
    __syncthreads();

#pragma unroll
    for (int j = 0; j < 4; j++) {
        int ny = ty + j * 8;
        __half* drow = dst + moff + (size_t)(n0 + ny) * 2048 + k0;
        drow[tx]      = __float2half(sm[tx][ny]);
        drow[tx + 32] = __float2half(sm[tx + 32][ny]);
    }
}

// ============================================================================
// x convert: f32 -> fp16
// ============================================================================
__global__ void cvtX_kernel(const float* __restrict__ src, __half* __restrict__ dst,
                            int n2) {
    for (int i = blockIdx.x * blockDim.x + threadIdx.x; i < n2;
         i += gridDim.x * blockDim.x) {
        float2 v = ((const float2*)src)[i];
        ((__half2*)dst)[i] = __floats2half2_rn(v.x, v.y);
    }
}

// ============================================================================
// zero routing counters
// ============================================================================
__global__ void zero_cnt() {
    if (threadIdx.x < NEXP) g_cnt[threadIdx.x] = 0;
}

// ============================================================================
// gate (fp32)
// ============================================================================
__global__ void gate_kernel(const float* __restrict__ x,
                            const float* __restrict__ gw,
                            const float* __restrict__ gb,
                            const float* __restrict__ biases) {
    const int t = blockIdx.x;
    const float* xr = x + (size_t)t * D_DIM;

    float p[NEXP];
#pragma unroll
    for (int e = 0; e < NEXP; e++) p[e] = 0.f;

    for (int i = threadIdx.x; i < D_DIM; i += 128) {
        float xv = xr[i];
        const float* g = gw + (size_t)i * NEXP;
#pragma unroll
        for (int e = 0; e < NEXP; e++) p[e] += xv * g[e];
    }
#pragma unroll
    for (int off = 16; off > 0; off >>= 1) {
#pragma unroll
        for (int e = 0; e < NEXP; e++)
            p[e] += __shfl_xor_sync(0xffffffffu, p[e], off);
    }

    __shared__ float sm[4][NEXP];
    const int wid = threadIdx.x >> 5, lane = threadIdx.x & 31;
    if (lane == 0) {
#pragma unroll
        for (int e = 0; e < NEXP; e++) sm[wid][e] = p[e];
    }
    __syncthreads();

    if (threadIdx.x == 0) {
        float logit[NEXP];
#pragma unroll
        for (int e = 0; e < NEXP; e++)
            logit[e] = sm[0][e] + sm[1][e] + sm[2][e] + sm[3][e] + gb[e];

        float mx = logit[0];
#pragma unroll
        for (int e = 1; e < NEXP; e++) mx = fmaxf(mx, logit[e]);
        float pr[NEXP], den = 0.f;
#pragma unroll
        for (int e = 0; e < NEXP; e++) { pr[e] = __expf(logit[e] - mx); den += pr[e]; }
#pragma unroll
        for (int e = 0; e < NEXP; e++) pr[e] /= den;

        float bi[NEXP];
#pragma unroll
        for (int e = 0; e < NEXP; e++) bi[e] = pr[e] + biases[e];

        bool used[NEXP] = {false, false, false, false, false, false, false};
        int sel[TOPK];
#pragma unroll
        for (int k = 0; k < TOPK; k++) {
            int best = -1; float bv = -1e30f;
#pragma unroll
            for (int e = 0; e < NEXP; e++)
                if (!used[e] && bi[e] > bv) { bv = bi[e]; best = e; }
            used[best] = true; sel[k] = best;
        }
        float ws = pr[sel[0]] + pr[sel[1]] + pr[sel[2]];

#pragma unroll
        for (int k = 0; k < TOPK; k++) {
            int e = sel[k];
            float w = pr[e] / ws;
            int pos = atomicAdd(&g_cnt[e], 1);
            g_idx[e][pos] = t;
            g_te[t][k] = e;
            g_tp[t][k] = pos;
            g_tw[t][k] = w;
        }
    }
}

// ============================================================================
// GEMM1 (all experts, fp16): act[z] = silu(Xg @ W1[z]) * (Xg @ Wg[z])
// 512 threads, 16 warps (4m x 4n), warp tile 32x32 per matrix.
// 3-stage cp.async pipeline, single sync/iter, ldmatrix fragment loads.
// ============================================================================
__global__ void __launch_bounds__(NTHREADS, 1)
gemm1_all() {
    extern __shared__ __half smemh[];
    const uint32_t sbase = (uint32_t)__cvta_generic_to_shared(smemh);
    const int z = blockIdx.z;

    const __half *B1p, *Bgp;
    int cnt;
    const int* idxp;
    if (z < NEXP) {
        B1p = g_w1h + (size_t)z * D_DIM * H_DIM;
        Bgp = g_wgh + (size_t)z * D_DIM * H_DIM;
        cnt = g_cnt[z];
        idxp = g_idx[z];
    } else {
        B1p = g_ws1h; Bgp = g_wsgh; cnt = T_TOK; idxp = nullptr;
    }

    const int m0 = blockIdx.x * BM;
    if (m0 >= cnt) return;
    const int n0 = blockIdx.y * BN;
    const int tid = threadIdx.x;

    int trow[2];
#pragma unroll
    for (int i = 0; i < 2; i++) {
        int r = m0 + ((tid + i * NTHREADS) >> 3);
        int t;
        if (idxp) t = (r < cnt) ? idxp[r] : 0;
        else      t = r;
        trow[i] = t;
    }

    auto load_stage = [&](int s, int k0) {
        const uint32_t xb = sbase + s * STAGE1B;
        const uint32_t b1 = xb + TILE_B;
        const uint32_t bg = b1 + TILE_B;
#pragma unroll
        for (int i = 0; i < 2; i++) {
            int c = tid + i * NTHREADS;
            int r = c >> 3, j = c & 7;
            cpa16(xb + (r * XSTRH + j * 8) * 2,
                  g_xh + (size_t)trow[i] * D_DIM + k0 + j * 8);
        }
#pragma unroll
        for (int i = 0; i < 2; i++) {
            int c = tid + i * NTHREADS;
            int r = c >> 3, j = c & 7;
            cpa16(b1 + (r * XSTRH + j * 8) * 2,
                  B1p + (size_t)(n0 + r) * D_DIM + k0 + j * 8);
            cpa16(bg + (r * XSTRH + j * 8) * 2,
                  Bgp + (size_t)(n0 + r) * D_DIM + k0 + j * 8);
        }
        cpa_commit();
    };

    float acc1[2][4][4];
    float accg[2][4][4];
#pragma unroll
    for (int i = 0; i < 2; i++)
#pragma unroll
        for (int j = 0; j < 4; j++)
#pragma unroll
            for (int r = 0; r < 4; r++) { acc1[i][j][r] = 0.f; accg[i][j][r] = 0.f; }

    const int wid = tid >> 5, lane = tid & 31;
    const int wm = (wid & 3) * 32, wn = (wid >> 2) * 32;
    const int qr = lane >> 2, qk = lane & 3;

    // ldmatrix lane address offsets (bytes from tile base)
    const int l8 = lane & 7;
    uint32_t a_off[2], b_off[2];
#pragma unroll
    for (int mf = 0; mf < 2; mf++)
        a_off[mf] = ((wm + mf * 16 + l8 + ((lane >> 3) & 1) * 8) * XSTRH
                     + ((lane >> 4) & 1) * 8) * 2;
#pragma unroll
    for (int p = 0; p < 2; p++)
        b_off[p] = ((wn + p * 16 + l8 + ((lane >> 4) & 1) * 8) * XSTRH
                    + ((lane >> 3) & 1) * 8) * 2;

    load_stage(0, 0);
    load_stage(1, BKH);
    for (int it = 0; it < NIT; ++it) {
        cpa_wait1();
        __syncthreads();
        if (it + NS1 - 1 < NIT) load_stage((it + NS1 - 1) % NS1, (it + NS1 - 1) * BKH);

        const uint32_t xb = sbase + (it % NS1) * STAGE1B;
        const uint32_t b1 = xb + TILE_B;
        const uint32_t bg = b1 + TILE_B;

#pragma unroll
        for (int kk = 0; kk < 4; kk++) {
            const int kb = kk * 32;       // 16 halfs per K-step
            uint32_t a[2][4];
#pragma unroll
            for (int mf = 0; mf < 2; mf++) LDSM4(a[mf], xb + a_off[mf] + kb);
#pragma unroll
            for (int p = 0; p < 2; p++) {
                uint32_t b[4], g[4];
                LDSM4(b, b1 + b_off[p] + kb);
                LDSM4(g, bg + b_off[p] + kb);
#pragma unroll
                for (int mf = 0; mf < 2; mf++) {
                    mma_f16(acc1[mf][2 * p],     a[mf], b[0], b[1]);
                    mma_f16(acc1[mf][2 * p + 1], a[mf], b[2], b[3]);
                    mma_f16(accg[mf][2 * p],     a[mf], g[0], g[1]);
                    mma_f16(accg[mf][2 * p + 1], a[mf], g[2], g[3]);
                }
            }
        }
    }

    // epilogue: fp16(silu(acc1)*accg) -> g_acth[z]
    __half* actp = g_acth[z];
#pragma unroll
    for (int mf = 0; mf < 2; mf++) {
        int r0 = m0 + wm + mf * 16 + qr;
        int r1 = r0 + 8;
#pragma unroll
        for (int nf = 0; nf < 4; nf++) {
            int cl = n0 + wn + nf * 8 + qk * 2;
            __half2 h0 = __floats2half2_rn(silu_f(acc1[mf][nf][0]) * accg[mf][nf][0],
                                           silu_f(acc1[mf][nf][1]) * accg[mf][nf][1]);
            __half2 h1 = __floats2half2_rn(silu_f(acc1[mf][nf][2]) * accg[mf][nf][2],
                                           silu_f(acc1[mf][nf][3]) * accg[mf][nf][3]);
            *(__half2*)(actp + (size_t)r0 * H_DIM + cl) = h0;
            *(__half2*)(actp + (size_t)r1 * H_DIM + cl) = h1;
        }
    }
}

// ============================================================================
// GEMM2 (all experts, fp16): y = act[z] @ W2[z]
// 512 threads, 16 warps (4m x 4n), warp tile 32x32.
// 4-stage cp.async pipeline, single sync/iter, ldmatrix fragment loads.
// ============================================================================
__global__ void __launch_bounds__(NTHREADS, 1)
gemm2_all(float* __restrict__ out) {
    extern __shared__ __half smemh[];
    const uint32_t sbase = (uint32_t)__cvta_generic_to_shared(smemh);
    const int z = blockIdx.z;

    const __half* Bp;
    int cnt;
    if (z < NEXP) { Bp = g_w2h + (size_t)z * H_DIM * D_DIM; cnt = g_cnt[z]; }
    else          { Bp = g_ws2h; cnt = T_TOK; }
    const __half* Ap = g_acth[z];

    const int m0 = blockIdx.x * BM;
    if (m0 >= cnt) return;
    const int n0 = blockIdx.y * BN;
    const int tid = threadIdx.x;

    auto load_stage = [&](int s, int k0) {
        const uint32_t ab = sbase + s * STAGE2B;
        const uint32_t bb = ab + TILE_B;
#pragma unroll
        for (int i = 0; i < 2; i++) {
            int c = tid + i * NTHREADS;
            int r = c >> 3, j = c & 7;
            cpa16(ab + (r * XSTRH + j * 8) * 2,
                  Ap + (size_t)(m0 + r) * H_DIM + k0 + j * 8);
        }
#pragma unroll
        for (int i = 0; i < 2; i++) {
            int c = tid + i * NTHREADS;
            int r = c >> 3, j = c & 7;
            cpa16(bb + (r * XSTRH + j * 8) * 2,
                  Bp + (size_t)(n0 + r) * H_DIM + k0 + j * 8);
        }
        cpa_commit();
    };

    float acc[2][4][4];
#pragma unroll
    for (int i = 0; i < 2; i++)
#pragma unroll
        for (int j = 0; j < 4; j++)
#pragma unroll
            for (int r = 0; r < 4; r++) acc[i][j][r] = 0.f;

    const int wid = tid >> 5, lane = tid & 31;
    const int wm = (wid & 3) * 32, wn = (wid >> 2) * 32;
    const int qr = lane >> 2, qk = lane & 3;

    const int l8 = lane & 7;
    uint32_t a_off[2], b_off[2];
#pragma unroll
    for (int mf = 0; mf < 2; mf++)
        a_off[mf] = ((wm + mf * 16 + l8 + ((lane >> 3) & 1) * 8) * XSTRH
                     + ((lane >> 4) & 1) * 8) * 2;
#pragma unroll
    for (int p = 0; p < 2; p++)
        b_off[p] = ((wn + p * 16 + l8 + ((lane >> 4) & 1) * 8) * XSTRH
                    + ((lane >> 3) & 1) * 8) * 2;

    load_stage(0, 0);
    load_stage(1, BKH);
    load_stage(2, 2 * BKH);
    for (int it = 0; it < NIT; ++it) {
        cpa_wait2();
        __syncthreads();
        if (it + NS2 - 1 < NIT) load_stage((it + NS2 - 1) % NS2, (it + NS2 - 1) * BKH);

        const uint32_t ab = sbase + (it % NS2) * STAGE2B;
        const uint32_t bb = ab + TILE_B;

#pragma unroll
        for (int kk = 0; kk < 4; kk++) {
            const int kb = kk * 32;
            uint32_t a[2][4];
#pragma unroll
            for (int mf = 0; mf < 2; mf++) LDSM4(a[mf], ab + a_off[mf] + kb);
#pragma unroll
            for (int p = 0; p < 2; p++) {
                uint32_t b[4];
                LDSM4(b, bb + b_off[p] + kb);
#pragma unroll
                for (int mf = 0; mf < 2; mf++) {
                    mma_f16(acc[mf][2 * p],     a[mf], b[0], b[1]);
                    mma_f16(acc[mf][2 * p + 1], a[mf], b[2], b[3]);
                }
            }
        }
    }

#pragma unroll
    for (int mf = 0; mf < 2; mf++) {
        int r0 = m0 + wm + mf * 16 + qr;
        int r1 = r0 + 8;
#pragma unroll
        for (int nf = 0; nf < 4; nf++) {
            int cl = n0 + wn + nf * 8 + qk * 2;
            float2 v0 = { acc[mf][nf][0], acc[mf][nf][1] };
            float2 v1 = { acc[mf][nf][2], acc[mf][nf][3] };
            if (z == NEXP) {
                *(float2*)(out + (size_t)r0 * D_DIM + cl) = v0;
                *(float2*)(out + (size_t)r1 * D_DIM + cl) = v1;
            } else {
                float* yp = g_y[z];
                if (r0 < cnt) *(float2*)(yp + (size_t)r0 * D_DIM + cl) = v0;
                if (r1 < cnt) *(float2*)(yp + (size_t)r1 * D_DIM + cl) = v1;
            }
        }
    }
}

// ============================================================================
// combine: out[t] += sum_k w_k * y[e_k][pos_k]
// ============================================================================
__global__ void combine_kernel(float* __restrict__ out) {
    const int t = blockIdx.x;
    const int e0 = g_te[t][0], e1 = g_te[t][1], e2 = g_te[t][2];
    const float w0 = g_tw[t][0], w1 = g_tw[t][1], w2 = g_tw[t][2];
    const float4* y0 = (const float4*)(g_y[e0] + (size_t)g_tp[t][0] * D_DIM);
    const float4* y1 = (const float4*)(g_y[e1] + (size_t)g_tp[t][1] * D_DIM);
    const float4* y2 = (const float4*)(g_y[e2] + (size_t)g_tp[t][2] * D_DIM);
    float4* o = (float4*)(out + (size_t)t * D_DIM);

    for (int i = threadIdx.x; i < D_DIM / 4; i += 256) {
        float4 v = o[i];
        float4 a = y0[i], b = y1[i], c = y2[i];
        v.x += w0 * a.x + w1 * b.x + w2 * c.x;
        v.y += w0 * a.y + w1 * b.y + w2 * c.y;
        v.z += w0 * a.z + w1 * b.z + w2 * c.z;
        v.w += w0 * a.w + w1 * b.w + w2 * c.w;
        o[i] = v;
    }
}

// ============================================================================
// launcher
// ============================================================================
extern "C" void kernel_launch(void* const* d_in, const int* in_sizes, int n_in,
                              void* d_out, int out_size) {
    const float* x    = (const float*)d_in[0];
    const float* W1   = (const float*)d_in[1];
    const float* Wg   = (const float*)d_in[2];
    const float* W2   = (const float*)d_in[3];
    const float* Ws1  = (const float*)d_in[4];
    const float* Wsg  = (const float*)d_in[5];
    const float* Ws2  = (const float*)d_in[6];
    const float* gw   = (const float*)d_in[7];
    const float* gb   = (const float*)d_in[8];
    const float* bias = (const float*)d_in[9];
    float* out = (float*)d_out;
    (void)in_sizes; (void)n_in; (void)out_size;

    cudaFuncSetAttribute(gemm1_all, cudaFuncAttributeMaxDynamicSharedMemorySize, SMEM1_BYTES);
    cudaFuncSetAttribute(gemm2_all, cudaFuncAttributeMaxDynamicSharedMemorySize, SMEM2_BYTES);

    __half *w1h, *wgh, *w2h, *ws1h, *wsgh, *ws2h, *xh;
    cudaGetSymbolAddress((void**)&w1h,  g_w1h);
    cudaGetSymbolAddress((void**)&wgh,  g_wgh);
    cudaGetSymbolAddress((void**)&w2h,  g_w2h);
    cudaGetSymbolAddress((void**)&ws1h, g_ws1h);
    cudaGetSymbolAddress((void**)&wsgh, g_wsgh);
    cudaGetSymbolAddress((void**)&ws2h, g_ws2h);
    cudaGetSymbolAddress((void**)&xh,   g_xh);

    dim3 tb(32, 8);
    cvtT_kernel<<<dim3(32, 64, NEXP), tb>>>(W1,  w1h);
    cvtT_kernel<<<dim3(32, 64, NEXP), tb>>>(Wg,  wgh);
    cvtT_kernel<<<dim3(32, 64, NEXP), tb>>>(W2,  w2h);
    cvtT_kernel<<<dim3(32, 64, 1),    tb>>>(Ws1, ws1h);
    cvtT_kernel<<<dim3(32, 64, 1),    tb>>>(Wsg, wsgh);
    cvtT_kernel<<<dim3(32, 64, 1),    tb>>>(Ws2, ws2h);
    cvtX_kernel<<<2048, 256>>>(x, xh, (int)(XELEMS / 2));

    zero_cnt<<<1, 32>>>();
    gate_kernel<<<T_TOK, 128>>>(x, gw, gb, bias);
    gemm1_all<<<dim3(T_TOK / BM, H_DIM / BN, 8), NTHREADS, SMEM1_BYTES>>>();
    gemm2_all<<<dim3(T_TOK / BM, D_DIM / BN, 8), NTHREADS, SMEM2_BYTES>>>(out);
    combine_kernel<<<T_TOK, 256>>>(out);
}

// round 8
// speedup vs baseline: 10.5838x; 1.0658x over previous
#include <cuda_runtime.h>
#include <cuda_fp16.h>
#include <cstdint>

// ---------------- problem constants ----------------
#define T_TOK 8192
#define D_DIM 2048
#define H_DIM 2048
#define NEXP  7
#define TOPK  3

// ---------------- tiling ----------------
#define BM 128
#define BN 128
#define BM2 256                // gemm2 M-tile
#define BKH 64                 // K-chunk in halfs (128B per row)
#define NTHREADS 512
#define XSTRH 72               // halfs per smem row (padded; conflict-free)
#define NIT (D_DIM / BKH)      // 32 k-iterations

#define TILE_B (128 * XSTRH * 2)        // bytes per 128-row tile = 18432
#define TILE_A2B (256 * XSTRH * 2)      // bytes per 256-row tile = 36864
#define STAGE1B (3 * TILE_B)            // gemm1 stage (A + B1 + Bg) = 55296
#define STAGE2B (TILE_A2B + TILE_B)     // gemm2 stage (A256 + B128) = 55296
#define NS1 3
#define NS2 3
#define SMEM1_BYTES (NS1 * STAGE1B)     // 165888
#define SMEM2_BYTES (NS2 * STAGE2B)     // 165888

#define WELEMS ((size_t)NEXP * D_DIM * H_DIM)
#define SELEMS ((size_t)D_DIM * H_DIM)
#define XELEMS ((size_t)T_TOK * D_DIM)

// ---------------- device scratch (no allocations allowed) ----------------
__device__ int   g_cnt[NEXP];
__device__ __align__(16) int   g_idx[NEXP][T_TOK];
__device__ int   g_te[T_TOK][TOPK];
__device__ int   g_tp[T_TOK][TOPK];
__device__ float g_tw[T_TOK][TOPK];

__device__ __align__(16) __half g_acth[8][(size_t)T_TOK * H_DIM];   // fp16 SwiGLU acts
__device__ __align__(16) float  g_y[NEXP][(size_t)T_TOK * D_DIM];   // staged routed outputs

// fp16 operands: weights TRANSPOSED to [n][k]; x row-major [m][k]
__device__ __align__(16) __half g_w1h[WELEMS];
__device__ __align__(16) __half g_wgh[WELEMS];
__device__ __align__(16) __half g_w2h[WELEMS];
__device__ __align__(16) __half g_ws1h[SELEMS];
__device__ __align__(16) __half g_wsgh[SELEMS];
__device__ __align__(16) __half g_ws2h[SELEMS];
__device__ __align__(16) __half g_xh[XELEMS];

// ---------------- helpers ----------------
__device__ __forceinline__ float silu_f(float z) {
    return z / (1.0f + __expf(-z));
}

__device__ __forceinline__ void mma_f16(float c[4], const uint32_t a[4],
                                        const uint32_t b0, const uint32_t b1) {
    asm volatile(
        "mma.sync.aligned.m16n8k16.row.col.f32.f16.f16.f32 "
        "{%0,%1,%2,%3}, {%4,%5,%6,%7}, {%8,%9}, {%0,%1,%2,%3};\n"
        : "+f"(c[0]), "+f"(c[1]), "+f"(c[2]), "+f"(c[3])
        : "r"(a[0]), "r"(a[1]), "r"(a[2]), "r"(a[3]),
          "r"(b0), "r"(b1));
}

#define LDSM4(r, addr) \
    asm volatile("ldmatrix.sync.aligned.m8n8.x4.shared.b16 {%0,%1,%2,%3}, [%4];" \
                 : "=r"((r)[0]), "=r"((r)[1]), "=r"((r)[2]), "=r"((r)[3]) \
                 : "r"(addr))

__device__ __forceinline__ void cpa16(uint32_t saddr, const void* gptr) {
    asm volatile("cp.async.cg.shared.global [%0], [%1], 16;\n" :: "r"(saddr), "l"(gptr));
}
__device__ __forceinline__ void cpa_commit() {
    asm volatile("cp.async.commit_group;\n" ::: "memory");
}
__device__ __forceinline__ void cpa_wait1() {
    asm volatile("cp.async.wait_group 1;\n" ::: "memory");
}

// ============================================================================
// weight convert + transpose, ALL matrices in one launch:
// z in [0,7)  -> W1[z], [7,14) -> Wg, [14,21) -> W2, 21 -> Ws1, 22 -> Wsg, 23 -> Ws2
// src f32 [K=2048][N=2048] -> dst fp16 [N][K]
// ============================================================================
__global__ void cvtT_all(const float* __restrict__ W1, const float* __restrict__ Wg,
                         const float* __restrict__ W2, const float* __restrict__ Ws1,
                         const float* __restrict__ Wsg, const float* __restrict__ Ws2,
                         __half* __restrict__ w1h, __half* __restrict__ wgh,
                         __half* __restrict__ w2h, __half* __restrict__ ws1h,
                         __half* __restrict__ wsgh, __half* __restrict__ ws2h) {
    __shared__ float sm[64][33];
    const int z = blockIdx.z;
    const float* src;
    __half* dst;
    if      (z < 7)  { src = W1 + (size_t)z * SELEMS;        dst = w1h + (size_t)z * SELEMS; }
    else if (z < 14) { src = Wg + (size_t)(z - 7) * SELEMS;  dst = wgh + (size_t)(z - 7) * SELEMS; }
    else if (z < 21) { src = W2 + (size_t)(z - 14) * SELEMS; dst = w2h + (size_t)(z - 14) * SELEMS; }
    else if (z == 21) { src = Ws1; dst = ws1h; }
    else if (z == 22) { src = Wsg; dst = wsgh; }
    else              { src = Ws2; dst = ws2h; }

    const int k0 = blockIdx.x * 64;
    const int n0 = blockIdx.y * 32;
    const int tx = threadIdx.x, ty = threadIdx.y;

#pragma unroll
    for (int i = 0; i < 8; i++) {
        int ky = ty + i * 8;
        sm[ky][tx] = src[(size_t)(k0 + ky) * 2048 + n0 + tx];
    }
    __syncthreads();

#pragma unroll
    for (int j = 0; j < 4; j++) {
        int ny = ty + j * 8;
        __half* drow = dst + (size_t)(n0 + ny) * 2048 + k0;
        drow[tx]      = __float2half(sm[tx][ny]);
        drow[tx + 32] = __float2half(sm[tx + 32][ny]);
    }
}

// ============================================================================
// x convert: f32 -> fp16
// ============================================================================
__global__ void cvtX_kernel(const float* __restrict__ src, __half* __restrict__ dst,
                            int n2) {
    for (int i = blockIdx.x * blockDim.x + threadIdx.x; i < n2;
         i += gridDim.x * blockDim.x) {
        float2 v = ((const float2*)src)[i];
        ((__half2*)dst)[i] = __floats2half2_rn(v.x, v.y);
    }
}

// ============================================================================
// zero routing counters
// ============================================================================
__global__ void zero_cnt() {
    if (threadIdx.x < NEXP) g_cnt[threadIdx.x] = 0;
}

// ============================================================================
// gate (fp32)
// ============================================================================
__global__ void gate_kernel(const float* __restrict__ x,
                            const float* __restrict__ gw,
                            const float* __restrict__ gb,
                            const float* __restrict__ biases) {
    const int t = blockIdx.x;
    const float* xr = x + (size_t)t * D_DIM;

    float p[NEXP];
#pragma unroll
    for (int e = 0; e < NEXP; e++) p[e] = 0.f;

    for (int i = threadIdx.x; i < D_DIM; i += 128) {
        float xv = xr[i];
        const float* g = gw + (size_t)i * NEXP;
#pragma unroll
        for (int e = 0; e < NEXP; e++) p[e] += xv * g[e];
    }
#pragma unroll
    for (int off = 16; off > 0; off >>= 1) {
#pragma unroll
        for (int e = 0; e < NEXP; e++)
            p[e] += __shfl_xor_sync(0xffffffffu, p[e], off);
    }

    __shared__ float sm[4][NEXP];
    const int wid = threadIdx.x >> 5, lane = threadIdx.x & 31;
    if (lane == 0) {
#pragma unroll
        for (int e = 0; e < NEXP; e++) sm[wid][e] = p[e];
    }
    __syncthreads();

    if (threadIdx.x == 0) {
        float logit[NEXP];
#pragma unroll
        for (int e = 0; e < NEXP; e++)
            logit[e] = sm[0][e] + sm[1][e] + sm[2][e] + sm[3][e] + gb[e];

        float mx = logit[0];
#pragma unroll
        for (int e = 1; e < NEXP; e++) mx = fmaxf(mx, logit[e]);
        float pr[NEXP], den = 0.f;
#pragma unroll
        for (int e = 0; e < NEXP; e++) { pr[e] = __expf(logit[e] - mx); den += pr[e]; }
#pragma unroll
        for (int e = 0; e < NEXP; e++) pr[e] /= den;

        float bi[NEXP];
#pragma unroll
        for (int e = 0; e < NEXP; e++) bi[e] = pr[e] + biases[e];

        bool used[NEXP] = {false, false, false, false, false, false, false};
        int sel[TOPK];
#pragma unroll
        for (int k = 0; k < TOPK; k++) {
            int best = -1; float bv = -1e30f;
#pragma unroll
            for (int e = 0; e < NEXP; e++)
                if (!used[e] && bi[e] > bv) { bv = bi[e]; best = e; }
            used[best] = true; sel[k] = best;
        }
        float ws = pr[sel[0]] + pr[sel[1]] + pr[sel[2]];

#pragma unroll
        for (int k = 0; k < TOPK; k++) {
            int e = sel[k];
            float w = pr[e] / ws;
            int pos = atomicAdd(&g_cnt[e], 1);
            g_idx[e][pos] = t;
            g_te[t][k] = e;
            g_tp[t][k] = pos;
            g_tw[t][k] = w;
        }
    }
}

// ============================================================================
// GEMM1 (all experts, fp16): act[z] = silu(Xg @ W1[z]) * (Xg @ Wg[z])
// Block 128x128, 512 threads, 16 warps (4m x 4n), warp tile 32x32 per matrix.
// ============================================================================
__global__ void __launch_bounds__(NTHREADS, 1)
gemm1_all() {
    extern __shared__ __half smemh[];
    const uint32_t sbase = (uint32_t)__cvta_generic_to_shared(smemh);
    const int z = blockIdx.z;

    const __half *B1p, *Bgp;
    int cnt;
    const int* idxp;
    if (z < NEXP) {
        B1p = g_w1h + (size_t)z * D_DIM * H_DIM;
        Bgp = g_wgh + (size_t)z * D_DIM * H_DIM;
        cnt = g_cnt[z];
        idxp = g_idx[z];
    } else {
        B1p = g_ws1h; Bgp = g_wsgh; cnt = T_TOK; idxp = nullptr;
    }

    const int m0 = blockIdx.x * BM;
    if (m0 >= cnt) return;
    const int n0 = blockIdx.y * BN;
    const int tid = threadIdx.x;

    int trow[2];
#pragma unroll
    for (int i = 0; i < 2; i++) {
        int r = m0 + ((tid + i * NTHREADS) >> 3);
        int t;
        if (idxp) t = (r < cnt) ? idxp[r] : 0;
        else      t = r;
        trow[i] = t;
    }

    auto load_stage = [&](int s, int k0) {
        const uint32_t xb = sbase + s * STAGE1B;
        const uint32_t b1 = xb + TILE_B;
        const uint32_t bg = b1 + TILE_B;
#pragma unroll
        for (int i = 0; i < 2; i++) {
            int c = tid + i * NTHREADS;
            int r = c >> 3, j = c & 7;
            cpa16(xb + (r * XSTRH + j * 8) * 2,
                  g_xh + (size_t)trow[i] * D_DIM + k0 + j * 8);
        }
#pragma unroll
        for (int i = 0; i < 2; i++) {
            int c = tid + i * NTHREADS;
            int r = c >> 3, j = c & 7;
            cpa16(b1 + (r * XSTRH + j * 8) * 2,
                  B1p + (size_t)(n0 + r) * D_DIM + k0 + j * 8);
            cpa16(bg + (r * XSTRH + j * 8) * 2,
                  Bgp + (size_t)(n0 + r) * D_DIM + k0 + j * 8);
        }
        cpa_commit();
    };

    float acc1[2][4][4];
    float accg[2][4][4];
#pragma unroll
    for (int i = 0; i < 2; i++)
#pragma unroll
        for (int j = 0; j < 4; j++)
#pragma unroll
            for (int r = 0; r < 4; r++) { acc1[i][j][r] = 0.f; accg[i][j][r] = 0.f; }

    const int wid = tid >> 5, lane = tid & 31;
    const int wm = (wid & 3) * 32, wn = (wid >> 2) * 32;
    const int qr = lane >> 2, qk = lane & 3;

    const int l8 = lane & 7;
    uint32_t a_off[2], b_off[2];
#pragma unroll
    for (int mf = 0; mf < 2; mf++)
        a_off[mf] = ((wm + mf * 16 + l8 + ((lane >> 3) & 1) * 8) * XSTRH
                     + ((lane >> 4) & 1) * 8) * 2;
#pragma unroll
    for (int p = 0; p < 2; p++)
        b_off[p] = ((wn + p * 16 + l8 + ((lane >> 4) & 1) * 8) * XSTRH
                    + ((lane >> 3) & 1) * 8) * 2;

    load_stage(0, 0);
    load_stage(1, BKH);
    for (int it = 0; it < NIT; ++it) {
        cpa_wait1();
        __syncthreads();
        if (it + NS1 - 1 < NIT) load_stage((it + NS1 - 1) % NS1, (it + NS1 - 1) * BKH);

        const uint32_t xb = sbase + (it % NS1) * STAGE1B;
        const uint32_t b1 = xb + TILE_B;
        const uint32_t bg = b1 + TILE_B;

#pragma unroll
        for (int kk = 0; kk < 4; kk++) {
            const int kb = kk * 32;
            uint32_t a[2][4];
#pragma unroll
            for (int mf = 0; mf < 2; mf++) LDSM4(a[mf], xb + a_off[mf] + kb);
#pragma unroll
            for (int p = 0; p < 2; p++) {
                uint32_t b[4], g[4];
                LDSM4(b, b1 + b_off[p] + kb);
                LDSM4(g, bg + b_off[p] + kb);
#pragma unroll
                for (int mf = 0; mf < 2; mf++) {
                    mma_f16(acc1[mf][2 * p],     a[mf], b[0], b[1]);
                    mma_f16(acc1[mf][2 * p + 1], a[mf], b[2], b[3]);
                    mma_f16(accg[mf][2 * p],     a[mf], g[0], g[1]);
                    mma_f16(accg[mf][2 * p + 1], a[mf], g[2], g[3]);
                }
            }
        }
    }

    __half* actp = g_acth[z];
#pragma unroll
    for (int mf = 0; mf < 2; mf++) {
        int r0 = m0 + wm + mf * 16 + qr;
        int r1 = r0 + 8;
#pragma unroll
        for (int nf = 0; nf < 4; nf++) {
            int cl = n0 + wn + nf * 8 + qk * 2;
            __half2 h0 = __floats2half2_rn(silu_f(acc1[mf][nf][0]) * accg[mf][nf][0],
                                           silu_f(acc1[mf][nf][1]) * accg[mf][nf][1]);
            __half2 h1 = __floats2half2_rn(silu_f(acc1[mf][nf][2]) * accg[mf][nf][2],
                                           silu_f(acc1[mf][nf][3]) * accg[mf][nf][3]);
            *(__half2*)(actp + (size_t)r0 * H_DIM + cl) = h0;
            *(__half2*)(actp + (size_t)r1 * H_DIM + cl) = h1;
        }
    }
}

// ============================================================================
// GEMM2 (all experts, fp16): y = act[z] @ W2[z]
// Block 256x128, 512 threads, 16 warps (4m x 4n), warp tile 64x32.
// ============================================================================
__global__ void __launch_bounds__(NTHREADS, 1)
gemm2_all(float* __restrict__ out) {
    extern __shared__ __half smemh[];
    const uint32_t sbase = (uint32_t)__cvta_generic_to_shared(smemh);
    const int z = blockIdx.z;

    const __half* Bp;
    int cnt;
    if (z < NEXP) { Bp = g_w2h + (size_t)z * H_DIM * D_DIM; cnt = g_cnt[z]; }
    else          { Bp = g_ws2h; cnt = T_TOK; }
    const __half* Ap = g_acth[z];

    const int m0 = blockIdx.x * BM2;
    if (m0 >= cnt) return;
    const int n0 = blockIdx.y * BN;
    const int tid = threadIdx.x;

    auto load_stage = [&](int s, int k0) {
        const uint32_t ab = sbase + s * STAGE2B;
        const uint32_t bb = ab + TILE_A2B;
#pragma unroll
        for (int i = 0; i < 4; i++) {          // 256 rows x 8 segs / 512 threads
            int c = tid + i * NTHREADS;
            int r = c >> 3, j = c & 7;
            cpa16(ab + (r * XSTRH + j * 8) * 2,
                  Ap + (size_t)(m0 + r) * H_DIM + k0 + j * 8);
        }
#pragma unroll
        for (int i = 0; i < 2; i++) {          // 128 rows x 8 segs / 512 threads
            int c = tid + i * NTHREADS;
            int r = c >> 3, j = c & 7;
            cpa16(bb + (r * XSTRH + j * 8) * 2,
                  Bp + (size_t)(n0 + r) * H_DIM + k0 + j * 8);
        }
        cpa_commit();
    };

    float acc[4][4][4];
#pragma unroll
    for (int i = 0; i < 4; i++)
#pragma unroll
        for (int j = 0; j < 4; j++)
#pragma unroll
            for (int r = 0; r < 4; r++) acc[i][j][r] = 0.f;

    const int wid = tid >> 5, lane = tid & 31;
    const int wm = (wid & 3) * 64, wn = (wid >> 2) * 32;
    const int qr = lane >> 2, qk = lane & 3;

    const int l8 = lane & 7;
    uint32_t a_off[4], b_off[2];
#pragma unroll
    for (int mf = 0; mf < 4; mf++)
        a_off[mf] = ((wm + mf * 16 + l8 + ((lane >> 3) & 1) * 8) * XSTRH
                     + ((lane >> 4) & 1) * 8) * 2;
#pragma unroll
    for (int p = 0; p < 2; p++)
        b_off[p] = ((wn + p * 16 + l8 + ((lane >> 4) & 1) * 8) * XSTRH
                    + ((lane >> 3) & 1) * 8) * 2;

    load_stage(0, 0);
    load_stage(1, BKH);
    for (int it = 0; it < NIT; ++it) {
        cpa_wait1();
        __syncthreads();
        if (it + NS2 - 1 < NIT) load_stage((it + NS2 - 1) % NS2, (it + NS2 - 1) * BKH);

        const uint32_t ab = sbase + (it % NS2) * STAGE2B;
        const uint32_t bb = ab + TILE_A2B;

#pragma unroll
        for (int kk = 0; kk < 4; kk++) {
            const int kb = kk * 32;
            uint32_t a[4][4];
#pragma unroll
            for (int mf = 0; mf < 4; mf++) LDSM4(a[mf], ab + a_off[mf] + kb);
#pragma unroll
            for (int p = 0; p < 2; p++) {
                uint32_t b[4];
                LDSM4(b, bb + b_off[p] + kb);
#pragma unroll
                for (int mf = 0; mf < 4; mf++) {
                    mma_f16(acc[mf][2 * p],     a[mf], b[0], b[1]);
                    mma_f16(acc[mf][2 * p + 1], a[mf], b[2], b[3]);
                }
            }
        }
    }

#pragma unroll
    for (int mf = 0; mf < 4; mf++) {
        int r0 = m0 + wm + mf * 16 + qr;
        int r1 = r0 + 8;
#pragma unroll
        for (int nf = 0; nf < 4; nf++) {
            int cl = n0 + wn + nf * 8 + qk * 2;
            float2 v0 = { acc[mf][nf][0], acc[mf][nf][1] };
            float2 v1 = { acc[mf][nf][2], acc[mf][nf][3] };
            if (z == NEXP) {
                *(float2*)(out + (size_t)r0 * D_DIM + cl) = v0;
                *(float2*)(out + (size_t)r1 * D_DIM + cl) = v1;
            } else {
                float* yp = g_y[z];
                if (r0 < cnt) *(float2*)(yp + (size_t)r0 * D_DIM + cl) = v0;
                if (r1 < cnt) *(float2*)(yp + (size_t)r1 * D_DIM + cl) = v1;
            }
        }
    }
}

// ============================================================================
// combine: out[t] += sum_k w_k * y[e_k][pos_k]
// ============================================================================
__global__ void combine_kernel(float* __restrict__ out) {
    const int t = blockIdx.x;
    const int e0 = g_te[t][0], e1 = g_te[t][1], e2 = g_te[t][2];
    const float w0 = g_tw[t][0], w1 = g_tw[t][1], w2 = g_tw[t][2];
    const float4* y0 = (const float4*)(g_y[e0] + (size_t)g_tp[t][0] * D_DIM);
    const float4* y1 = (const float4*)(g_y[e1] + (size_t)g_tp[t][1] * D_DIM);
    const float4* y2 = (const float4*)(g_y[e2] + (size_t)g_tp[t][2] * D_DIM);
    float4* o = (float4*)(out + (size_t)t * D_DIM);

    for (int i = threadIdx.x; i < D_DIM / 4; i += 256) {
        float4 v = o[i];
        float4 a = y0[i], b = y1[i], c = y2[i];
        v.x += w0 * a.x + w1 * b.x + w2 * c.x;
        v.y += w0 * a.y + w1 * b.y + w2 * c.y;
        v.z += w0 * a.z + w1 * b.z + w2 * c.z;
        v.w += w0 * a.w + w1 * b.w + w2 * c.w;
        o[i] = v;
    }
}

// ============================================================================
// launcher — order keeps gemm2_all as the 6th launch (ncu -s 5 -c 1)
// ============================================================================
extern "C" void kernel_launch(void* const* d_in, const int* in_sizes, int n_in,
                              void* d_out, int out_size) {
    const float* x    = (const float*)d_in[0];
    const float* W1   = (const float*)d_in[1];
    const float* Wg   = (const float*)d_in[2];
    const float* W2   = (const float*)d_in[3];
    const float* Ws1  = (const float*)d_in[4];
    const float* Wsg  = (const float*)d_in[5];
    const float* Ws2  = (const float*)d_in[6];
    const float* gw   = (const float*)d_in[7];
    const float* gb   = (const float*)d_in[8];
    const float* bias = (const float*)d_in[9];
    float* out = (float*)d_out;
    (void)in_sizes; (void)n_in; (void)out_size;

    cudaFuncSetAttribute(gemm1_all, cudaFuncAttributeMaxDynamicSharedMemorySize, SMEM1_BYTES);
    cudaFuncSetAttribute(gemm2_all, cudaFuncAttributeMaxDynamicSharedMemorySize, SMEM2_BYTES);

    __half *w1h, *wgh, *w2h, *ws1h, *wsgh, *ws2h, *xh;
    cudaGetSymbolAddress((void**)&w1h,  g_w1h);
    cudaGetSymbolAddress((void**)&wgh,  g_wgh);
    cudaGetSymbolAddress((void**)&w2h,  g_w2h);
    cudaGetSymbolAddress((void**)&ws1h, g_ws1h);
    cudaGetSymbolAddress((void**)&wsgh, g_wsgh);
    cudaGetSymbolAddress((void**)&ws2h, g_ws2h);
    cudaGetSymbolAddress((void**)&xh,   g_xh);

    // 1: all weight converts in one launch
    cvtT_all<<<dim3(32, 64, 24), dim3(32, 8)>>>(W1, Wg, W2, Ws1, Wsg, Ws2,
                                                w1h, wgh, w2h, ws1h, wsgh, ws2h);
    // 2-4
    cvtX_kernel<<<2048, 256>>>(x, xh, (int)(XELEMS / 2));
    zero_cnt<<<1, 32>>>();
    gate_kernel<<<T_TOK, 128>>>(x, gw, gb, bias);
    // 5-6 (ncu captures launch #6 = gemm2_all)
    gemm1_all<<<dim3(T_TOK / BM, H_DIM / BN, 8), NTHREADS, SMEM1_BYTES>>>();
    gemm2_all<<<dim3(T_TOK / BM2, D_DIM / BN, 8), NTHREADS, SMEM2_BYTES>>>(out);
    // 7
    combine_kernel<<<T_TOK, 256>>>(out);
}

// round 9
// speedup vs baseline: 10.6116x; 1.0026x over previous
#include <cuda_runtime.h>
#include <cuda_fp16.h>
#include <cstdint>

// ---------------- problem constants ----------------
#define T_TOK 8192
#define D_DIM 2048
#define H_DIM 2048
#define NEXP  7
#define TOPK  3

// ---------------- tiling ----------------
#define BM 128
#define BN 128
#define BM2 256                // gemm2 M-tile
#define BKH 64                 // K-chunk in halfs (128B per row)
#define NTHREADS 512
#define XSTRH 72               // halfs per smem row (padded; conflict-free)
#define NIT (D_DIM / BKH)      // 32 k-iterations

#define TILE_B (128 * XSTRH * 2)        // bytes per 128-row tile = 18432
#define TILE_A2B (256 * XSTRH * 2)      // bytes per 256-row tile = 36864
#define STAGE1B (3 * TILE_B)            // gemm1 stage (A + B1 + Bg) = 55296
#define STAGE2B (TILE_A2B + TILE_B)     // gemm2 stage (A256 + B128) = 55296
#define NS1 3
#define NS2 3
#define SMEM1_BYTES (NS1 * STAGE1B)     // 165888
#define SMEM2_BYTES (NS2 * STAGE2B)     // 165888

#define WELEMS ((size_t)NEXP * D_DIM * H_DIM)
#define SELEMS ((size_t)D_DIM * H_DIM)
#define XELEMS ((size_t)T_TOK * D_DIM)

// ---------------- device scratch (no allocations allowed) ----------------
__device__ int   g_cnt[NEXP];
__device__ __align__(16) int   g_idx[NEXP][T_TOK];
__device__ int   g_te[T_TOK][TOPK];
__device__ int   g_tp[T_TOK][TOPK];
__device__ float g_tw[T_TOK][TOPK];

__device__ __align__(16) __half g_acth[8][(size_t)T_TOK * H_DIM];   // fp16 SwiGLU acts
__device__ __align__(16) __half g_y[NEXP][(size_t)T_TOK * D_DIM];   // staged routed outputs (fp16)

// fp16 operands: weights TRANSPOSED to [n][k]; x row-major [m][k]
__device__ __align__(16) __half g_w1h[WELEMS];
__device__ __align__(16) __half g_wgh[WELEMS];
__device__ __align__(16) __half g_w2h[WELEMS];
__device__ __align__(16) __half g_ws1h[SELEMS];
__device__ __align__(16) __half g_wsgh[SELEMS];
__device__ __align__(16) __half g_ws2h[SELEMS];
__device__ __align__(16) __half g_xh[XELEMS];

// ---------------- helpers ----------------
__device__ __forceinline__ float silu_f(float z) {
    return z / (1.0f + __expf(-z));
}

__device__ __forceinline__ void mma_f16(float c[4], const uint32_t a[4],
                                        const uint32_t b0, const uint32_t b1) {
    asm volatile(
        "mma.sync.aligned.m16n8k16.row.col.f32.f16.f16.f32 "
        "{%0,%1,%2,%3}, {%4,%5,%6,%7}, {%8,%9}, {%0,%1,%2,%3};\n"
        : "+f"(c[0]), "+f"(c[1]), "+f"(c[2]), "+f"(c[3])
        : "r"(a[0]), "r"(a[1]), "r"(a[2]), "r"(a[3]),
          "r"(b0), "r"(b1));
}

#define LDSM4(r, addr) \
    asm volatile("ldmatrix.sync.aligned.m8n8.x4.shared.b16 {%0,%1,%2,%3}, [%4];" \
                 : "=r"((r)[0]), "=r"((r)[1]), "=r"((r)[2]), "=r"((r)[3]) \
                 : "r"(addr))

__device__ __forceinline__ void cpa16(uint32_t saddr, const void* gptr) {
    asm volatile("cp.async.cg.shared.global [%0], [%1], 16;\n" :: "r"(saddr), "l"(gptr));
}
__device__ __forceinline__ void cpa_commit() {
    asm volatile("cp.async.commit_group;\n" ::: "memory");
}
__device__ __forceinline__ void cpa_wait1() {
    asm volatile("cp.async.wait_group 1;\n" ::: "memory");
}

// ============================================================================
// weight convert + transpose, ALL matrices in one launch:
// z in [0,7) -> W1[z], [7,14) -> Wg, [14,21) -> W2, 21 -> Ws1, 22 -> Wsg, 23 -> Ws2
// ============================================================================
__global__ void cvtT_all(const float* __restrict__ W1, const float* __restrict__ Wg,
                         const float* __restrict__ W2, const float* __restrict__ Ws1,
                         const float* __restrict__ Wsg, const float* __restrict__ Ws2,
                         __half* __restrict__ w1h, __half* __restrict__ wgh,
                         __half* __restrict__ w2h, __half* __restrict__ ws1h,
                         __half* __restrict__ wsgh, __half* __restrict__ ws2h) {
    __shared__ float sm[64][33];
    const int z = blockIdx.z;
    const float* src;
    __half* dst;
    if      (z < 7)  { src = W1 + (size_t)z * SELEMS;        dst = w1h + (size_t)z * SELEMS; }
    else if (z < 14) { src = Wg + (size_t)(z - 7) * SELEMS;  dst = wgh + (size_t)(z - 7) * SELEMS; }
    else if (z < 21) { src = W2 + (size_t)(z - 14) * SELEMS; dst = w2h + (size_t)(z - 14) * SELEMS; }
    else if (z == 21) { src = Ws1; dst = ws1h; }
    else if (z == 22) { src = Wsg; dst = wsgh; }
    else              { src = Ws2; dst = ws2h; }

    const int k0 = blockIdx.x * 64;
    const int n0 = blockIdx.y * 32;
    const int tx = threadIdx.x, ty = threadIdx.y;

#pragma unroll
    for (int i = 0; i < 8; i++) {
        int ky = ty + i * 8;
        sm[ky][tx] = src[(size_t)(k0 + ky) * 2048 + n0 + tx];
    }
    __syncthreads();

#pragma unroll
    for (int j = 0; j < 4; j++) {
        int ny = ty + j * 8;
        __half* drow = dst + (size_t)(n0 + ny) * 2048 + k0;
        drow[tx]      = __float2half(sm[tx][ny]);
        drow[tx + 32] = __float2half(sm[tx + 32][ny]);
    }
}

// ============================================================================
// zero routing counters
// ============================================================================
__global__ void zero_cnt() {
    if (threadIdx.x < NEXP) g_cnt[threadIdx.x] = 0;
}

// ============================================================================
// FUSED gate + x-convert: one block per token.
// Reads the fp32 row once: writes fp16 row AND computes routing.
// ============================================================================
__global__ void __launch_bounds__(256) gate_cvt(const float* __restrict__ x,
                                                const float* __restrict__ gw,
                                                const float* __restrict__ gb,
                                                const float* __restrict__ biases) {
    const int t = blockIdx.x;
    const float4* xr = (const float4*)(x + (size_t)t * D_DIM);
    __half2* xo = (__half2*)(g_xh + (size_t)t * D_DIM);

    float p[NEXP];
#pragma unroll
    for (int e = 0; e < NEXP; e++) p[e] = 0.f;

#pragma unroll
    for (int i = 0; i < 2; i++) {
        int idx = threadIdx.x + i * 256;          // float4 index, 0..511
        float4 v = xr[idx];
        xo[idx * 2]     = __floats2half2_rn(v.x, v.y);
        xo[idx * 2 + 1] = __floats2half2_rn(v.z, v.w);
        const float* g0 = gw + (size_t)(idx * 4) * NEXP;
#pragma unroll
        for (int e = 0; e < NEXP; e++)
            p[e] += v.x * g0[e] + v.y * g0[NEXP + e] + v.z * g0[2 * NEXP + e]
                  + v.w * g0[3 * NEXP + e];
    }

#pragma unroll
    for (int off = 16; off > 0; off >>= 1) {
#pragma unroll
        for (int e = 0; e < NEXP; e++)
            p[e] += __shfl_xor_sync(0xffffffffu, p[e], off);
    }

    __shared__ float sm[8][NEXP];
    const int wid = threadIdx.x >> 5, lane = threadIdx.x & 31;
    if (lane == 0) {
#pragma unroll
        for (int e = 0; e < NEXP; e++) sm[wid][e] = p[e];
    }
    __syncthreads();

    if (threadIdx.x == 0) {
        float logit[NEXP];
#pragma unroll
        for (int e = 0; e < NEXP; e++) {
            float s = gb[e];
#pragma unroll
            for (int w = 0; w < 8; w++) s += sm[w][e];
            logit[e] = s;
        }

        float mx = logit[0];
#pragma unroll
        for (int e = 1; e < NEXP; e++) mx = fmaxf(mx, logit[e]);
        float pr[NEXP], den = 0.f;
#pragma unroll
        for (int e = 0; e < NEXP; e++) { pr[e] = __expf(logit[e] - mx); den += pr[e]; }
#pragma unroll
        for (int e = 0; e < NEXP; e++) pr[e] /= den;

        float bi[NEXP];
#pragma unroll
        for (int e = 0; e < NEXP; e++) bi[e] = pr[e] + biases[e];

        bool used[NEXP] = {false, false, false, false, false, false, false};
        int sel[TOPK];
#pragma unroll
        for (int k = 0; k < TOPK; k++) {
            int best = -1; float bv = -1e30f;
#pragma unroll
            for (int e = 0; e < NEXP; e++)
                if (!used[e] && bi[e] > bv) { bv = bi[e]; best = e; }
            used[best] = true; sel[k] = best;
        }
        float ws = pr[sel[0]] + pr[sel[1]] + pr[sel[2]];

#pragma unroll
        for (int k = 0; k < TOPK; k++) {
            int e = sel[k];
            float w = pr[e] / ws;
            int pos = atomicAdd(&g_cnt[e], 1);
            g_idx[e][pos] = t;
            g_te[t][k] = e;
            g_tp[t][k] = pos;
            g_tw[t][k] = w;
        }
    }
}

// ============================================================================
// GEMM1 (all experts, fp16): act[z] = silu(Xg @ W1[z]) * (Xg @ Wg[z])
// Block 128x128, 512 threads, 16 warps (4m x 4n), warp tile 32x32 per matrix.
// ============================================================================
__global__ void __launch_bounds__(NTHREADS, 1)
gemm1_all() {
    extern __shared__ __half smemh[];
    const uint32_t sbase = (uint32_t)__cvta_generic_to_shared(smemh);
    const int z = blockIdx.z;

    const __half *B1p, *Bgp;
    int cnt;
    const int* idxp;
    if (z < NEXP) {
        B1p = g_w1h + (size_t)z * D_DIM * H_DIM;
        Bgp = g_wgh + (size_t)z * D_DIM * H_DIM;
        cnt = g_cnt[z];
        idxp = g_idx[z];
    } else {
        B1p = g_ws1h; Bgp = g_wsgh; cnt = T_TOK; idxp = nullptr;
    }

    const int m0 = blockIdx.x * BM;
    if (m0 >= cnt) return;
    const int n0 = blockIdx.y * BN;
    const int tid = threadIdx.x;

    int trow[2];
#pragma unroll
    for (int i = 0; i < 2; i++) {
        int r = m0 + ((tid + i * NTHREADS) >> 3);
        int t;
        if (idxp) t = (r < cnt) ? idxp[r] : 0;
        else      t = r;
        trow[i] = t;
    }

    auto load_stage = [&](int s, int k0) {
        const uint32_t xb = sbase + s * STAGE1B;
        const uint32_t b1 = xb + TILE_B;
        const uint32_t bg = b1 + TILE_B;
#pragma unroll
        for (int i = 0; i < 2; i++) {
            int c = tid + i * NTHREADS;
            int r = c >> 3, j = c & 7;
            cpa16(xb + (r * XSTRH + j * 8) * 2,
                  g_xh + (size_t)trow[i] * D_DIM + k0 + j * 8);
        }
#pragma unroll
        for (int i = 0; i < 2; i++) {
            int c = tid + i * NTHREADS;
            int r = c >> 3, j = c & 7;
            cpa16(b1 + (r * XSTRH + j * 8) * 2,
                  B1p + (size_t)(n0 + r) * D_DIM + k0 + j * 8);
            cpa16(bg + (r * XSTRH + j * 8) * 2,
                  Bgp + (size_t)(n0 + r) * D_DIM + k0 + j * 8);
        }
        cpa_commit();
    };

    float acc1[2][4][4];
    float accg[2][4][4];
#pragma unroll
    for (int i = 0; i < 2; i++)
#pragma unroll
        for (int j = 0; j < 4; j++)
#pragma unroll
            for (int r = 0; r < 4; r++) { acc1[i][j][r] = 0.f; accg[i][j][r] = 0.f; }

    const int wid = tid >> 5, lane = tid & 31;
    const int wm = (wid & 3) * 32, wn = (wid >> 2) * 32;
    const int qr = lane >> 2, qk = lane & 3;

    const int l8 = lane & 7;
    uint32_t a_off[2], b_off[2];
#pragma unroll
    for (int mf = 0; mf < 2; mf++)
        a_off[mf] = ((wm + mf * 16 + l8 + ((lane >> 3) & 1) * 8) * XSTRH
                     + ((lane >> 4) & 1) * 8) * 2;
#pragma unroll
    for (int p = 0; p < 2; p++)
        b_off[p] = ((wn + p * 16 + l8 + ((lane >> 4) & 1) * 8) * XSTRH
                    + ((lane >> 3) & 1) * 8) * 2;

    load_stage(0, 0);
    load_stage(1, BKH);
    for (int it = 0; it < NIT; ++it) {
        cpa_wait1();
        __syncthreads();
        if (it + NS1 - 1 < NIT) load_stage((it + NS1 - 1) % NS1, (it + NS1 - 1) * BKH);

        const uint32_t xb = sbase + (it % NS1) * STAGE1B;
        const uint32_t b1 = xb + TILE_B;
        const uint32_t bg = b1 + TILE_B;

#pragma unroll
        for (int kk = 0; kk < 4; kk++) {
            const int kb = kk * 32;
            uint32_t a[2][4];
#pragma unroll
            for (int mf = 0; mf < 2; mf++) LDSM4(a[mf], xb + a_off[mf] + kb);
#pragma unroll
            for (int p = 0; p < 2; p++) {
                uint32_t b[4], g[4];
                LDSM4(b, b1 + b_off[p] + kb);
                LDSM4(g, bg + b_off[p] + kb);
#pragma unroll
                for (int mf = 0; mf < 2; mf++) {
                    mma_f16(acc1[mf][2 * p],     a[mf], b[0], b[1]);
                    mma_f16(acc1[mf][2 * p + 1], a[mf], b[2], b[3]);
                    mma_f16(accg[mf][2 * p],     a[mf], g[0], g[1]);
                    mma_f16(accg[mf][2 * p + 1], a[mf], g[2], g[3]);
                }
            }
        }
    }

    __half* actp = g_acth[z];
#pragma unroll
    for (int mf = 0; mf < 2; mf++) {
        int r0 = m0 + wm + mf * 16 + qr;
        int r1 = r0 + 8;
#pragma unroll
        for (int nf = 0; nf < 4; nf++) {
            int cl = n0 + wn + nf * 8 + qk * 2;
            __half2 h0 = __floats2half2_rn(silu_f(acc1[mf][nf][0]) * accg[mf][nf][0],
                                           silu_f(acc1[mf][nf][1]) * accg[mf][nf][1]);
            __half2 h1 = __floats2half2_rn(silu_f(acc1[mf][nf][2]) * accg[mf][nf][2],
                                           silu_f(acc1[mf][nf][3]) * accg[mf][nf][3]);
            *(__half2*)(actp + (size_t)r0 * H_DIM + cl) = h0;
            *(__half2*)(actp + (size_t)r1 * H_DIM + cl) = h1;
        }
    }
}

// ============================================================================
// GEMM2 (all experts, fp16): y = act[z] @ W2[z]
// Block 256x128, 512 threads, 16 warps (4m x 4n), warp tile 64x32.
// Routed outputs staged as fp16; shared expert written f32 to out.
// ============================================================================
__global__ void __launch_bounds__(NTHREADS, 1)
gemm2_all(float* __restrict__ out) {
    extern __shared__ __half smemh[];
    const uint32_t sbase = (uint32_t)__cvta_generic_to_shared(smemh);
    const int z = blockIdx.z;

    const __half* Bp;
    int cnt;
    if (z < NEXP) { Bp = g_w2h + (size_t)z * H_DIM * D_DIM; cnt = g_cnt[z]; }
    else          { Bp = g_ws2h; cnt = T_TOK; }
    const __half* Ap = g_acth[z];

    const int m0 = blockIdx.x * BM2;
    if (m0 >= cnt) return;
    const int n0 = blockIdx.y * BN;
    const int tid = threadIdx.x;

    auto load_stage = [&](int s, int k0) {
        const uint32_t ab = sbase + s * STAGE2B;
        const uint32_t bb = ab + TILE_A2B;
#pragma unroll
        for (int i = 0; i < 4; i++) {
            int c = tid + i * NTHREADS;
            int r = c >> 3, j = c & 7;
            cpa16(ab + (r * XSTRH + j * 8) * 2,
                  Ap + (size_t)(m0 + r) * H_DIM + k0 + j * 8);
        }
#pragma unroll
        for (int i = 0; i < 2; i++) {
            int c = tid + i * NTHREADS;
            int r = c >> 3, j = c & 7;
            cpa16(bb + (r * XSTRH + j * 8) * 2,
                  Bp + (size_t)(n0 + r) * H_DIM + k0 + j * 8);
        }
        cpa_commit();
    };

    float acc[4][4][4];
#pragma unroll
    for (int i = 0; i < 4; i++)
#pragma unroll
        for (int j = 0; j < 4; j++)
#pragma unroll
            for (int r = 0; r < 4; r++) acc[i][j][r] = 0.f;

    const int wid = tid >> 5, lane = tid & 31;
    const int wm = (wid & 3) * 64, wn = (wid >> 2) * 32;
    const int qr = lane >> 2, qk = lane & 3;

    const int l8 = lane & 7;
    uint32_t a_off[4], b_off[2];
#pragma unroll
    for (int mf = 0; mf < 4; mf++)
        a_off[mf] = ((wm + mf * 16 + l8 + ((lane >> 3) & 1) * 8) * XSTRH
                     + ((lane >> 4) & 1) * 8) * 2;
#pragma unroll
    for (int p = 0; p < 2; p++)
        b_off[p] = ((wn + p * 16 + l8 + ((lane >> 4) & 1) * 8) * XSTRH
                    + ((lane >> 3) & 1) * 8) * 2;

    load_stage(0, 0);
    load_stage(1, BKH);
    for (int it = 0; it < NIT; ++it) {
        cpa_wait1();
        __syncthreads();
        if (it + NS2 - 1 < NIT) load_stage((it + NS2 - 1) % NS2, (it + NS2 - 1) * BKH);

        const uint32_t ab = sbase + (it % NS2) * STAGE2B;
        const uint32_t bb = ab + TILE_A2B;

#pragma unroll
        for (int kk = 0; kk < 4; kk++) {
            const int kb = kk * 32;
            uint32_t a[4][4];
#pragma unroll
            for (int mf = 0; mf < 4; mf++) LDSM4(a[mf], ab + a_off[mf] + kb);
#pragma unroll
            for (int p = 0; p < 2; p++) {
                uint32_t b[4];
                LDSM4(b, bb + b_off[p] + kb);
#pragma unroll
                for (int mf = 0; mf < 4; mf++) {
                    mma_f16(acc[mf][2 * p],     a[mf], b[0], b[1]);
                    mma_f16(acc[mf][2 * p + 1], a[mf], b[2], b[3]);
                }
            }
        }
    }

#pragma unroll
    for (int mf = 0; mf < 4; mf++) {
        int r0 = m0 + wm + mf * 16 + qr;
        int r1 = r0 + 8;
#pragma unroll
        for (int nf = 0; nf < 4; nf++) {
            int cl = n0 + wn + nf * 8 + qk * 2;
            if (z == NEXP) {
                float2 v0 = { acc[mf][nf][0], acc[mf][nf][1] };
                float2 v1 = { acc[mf][nf][2], acc[mf][nf][3] };
                *(float2*)(out + (size_t)r0 * D_DIM + cl) = v0;
                *(float2*)(out + (size_t)r1 * D_DIM + cl) = v1;
            } else {
                __half* yp = g_y[z];
                if (r0 < cnt)
                    *(__half2*)(yp + (size_t)r0 * D_DIM + cl) =
                        __floats2half2_rn(acc[mf][nf][0], acc[mf][nf][1]);
                if (r1 < cnt)
                    *(__half2*)(yp + (size_t)r1 * D_DIM + cl) =
                        __floats2half2_rn(acc[mf][nf][2], acc[mf][nf][3]);
            }
        }
    }
}

// ============================================================================
// combine: out[t] += sum_k w_k * y[e_k][pos_k]   (y in fp16, uint4 = 8 halfs)
// ============================================================================
__global__ void __launch_bounds__(256) combine_kernel(float* __restrict__ out) {
    const int t = blockIdx.x;
    const int e0 = g_te[t][0], e1 = g_te[t][1], e2 = g_te[t][2];
    const float w0 = g_tw[t][0], w1 = g_tw[t][1], w2 = g_tw[t][2];
    const uint4* y0 = (const uint4*)(g_y[e0] + (size_t)g_tp[t][0] * D_DIM);
    const uint4* y1 = (const uint4*)(g_y[e1] + (size_t)g_tp[t][1] * D_DIM);
    const uint4* y2 = (const uint4*)(g_y[e2] + (size_t)g_tp[t][2] * D_DIM);
    float4* o = (float4*)(out + (size_t)t * D_DIM);

    const int i = threadIdx.x;          // 256 threads x 8 elems = 2048
    uint4 a = y0[i], b = y1[i], c = y2[i];
    float4 v0 = o[i * 2], v1 = o[i * 2 + 1];

    const __half2* ah = (const __half2*)&a;
    const __half2* bh = (const __half2*)&b;
    const __half2* ch = (const __half2*)&c;

    float2 f;
    f = __half22float2(ah[0]); v0.x += w0 * f.x; v0.y += w0 * f.y;
    f = __half22float2(ah[1]); v0.z += w0 * f.x; v0.w += w0 * f.y;
    f = __half22float2(ah[2]); v1.x += w0 * f.x; v1.y += w0 * f.y;
    f = __half22float2(ah[3]); v1.z += w0 * f.x; v1.w += w0 * f.y;

    f = __half22float2(bh[0]); v0.x += w1 * f.x; v0.y += w1 * f.y;
    f = __half22float2(bh[1]); v0.z += w1 * f.x; v0.w += w1 * f.y;
    f = __half22float2(bh[2]); v1.x += w1 * f.x; v1.y += w1 * f.y;
    f = __half22float2(bh[3]); v1.z += w1 * f.x; v1.w += w1 * f.y;

    f = __half22float2(ch[0]); v0.x += w2 * f.x; v0.y += w2 * f.y;
    f = __half22float2(ch[1]); v0.z += w2 * f.x; v0.w += w2 * f.y;
    f = __half22float2(ch[2]); v1.x += w2 * f.x; v1.y += w2 * f.y;
    f = __half22float2(ch[3]); v1.z += w2 * f.x; v1.w += w2 * f.y;

    o[i * 2]     = v0;
    o[i * 2 + 1] = v1;
}

// ============================================================================
// launcher
// ============================================================================
extern "C" void kernel_launch(void* const* d_in, const int* in_sizes, int n_in,
                              void* d_out, int out_size) {
    const float* x    = (const float*)d_in[0];
    const float* W1   = (const float*)d_in[1];
    const float* Wg   = (const float*)d_in[2];
    const float* W2   = (const float*)d_in[3];
    const float* Ws1  = (const float*)d_in[4];
    const float* Wsg  = (const float*)d_in[5];
    const float* Ws2  = (const float*)d_in[6];
    const float* gw   = (const float*)d_in[7];
    const float* gb   = (const float*)d_in[8];
    const float* bias = (const float*)d_in[9];
    float* out = (float*)d_out;
    (void)in_sizes; (void)n_in; (void)out_size;

    cudaFuncSetAttribute(gemm1_all, cudaFuncAttributeMaxDynamicSharedMemorySize, SMEM1_BYTES);
    cudaFuncSetAttribute(gemm2_all, cudaFuncAttributeMaxDynamicSharedMemorySize, SMEM2_BYTES);

    __half *w1h, *wgh, *w2h, *ws1h, *wsgh, *ws2h;
    cudaGetSymbolAddress((void**)&w1h,  g_w1h);
    cudaGetSymbolAddress((void**)&wgh,  g_wgh);
    cudaGetSymbolAddress((void**)&w2h,  g_w2h);
    cudaGetSymbolAddress((void**)&ws1h, g_ws1h);
    cudaGetSymbolAddress((void**)&wsgh, g_wsgh);
    cudaGetSymbolAddress((void**)&ws2h, g_ws2h);

    // 1: all weight converts
    cvtT_all<<<dim3(32, 64, 24), dim3(32, 8)>>>(W1, Wg, W2, Ws1, Wsg, Ws2,
                                                w1h, wgh, w2h, ws1h, wsgh, ws2h);
    // 2-3: routing (+ fused x convert)
    zero_cnt<<<1, 32>>>();
    gate_cvt<<<T_TOK, 256>>>(x, gw, gb, bias);
    // 4-5: expert FFNs
    gemm1_all<<<dim3(T_TOK / BM, H_DIM / BN, 8), NTHREADS, SMEM1_BYTES>>>();
    gemm2_all<<<dim3(T_TOK / BM2, D_DIM / BN, 8), NTHREADS, SMEM2_BYTES>>>(out);
    // 6: combine
    combine_kernel<<<T_TOK, 256>>>(out);
}